// round 5
// baseline (speedup 1.0000x reference)
#include <cuda_runtime.h>
#include <cuda_bf16.h>
#include <mma.h>
#include <cstdint>

// ---------------------------------------------------------------------------
// SMPL fused pipeline, round 5: both GEMMs on WMMA bf16x3, lean builds.
// ---------------------------------------------------------------------------

namespace smpl {

constexpr int V    = 6890;
constexpr int NB   = 10;
constexpr int NJ   = 24;
constexpr int NK   = 19;
constexpr int B    = 1024;

constexpr int VP   = 6912;            // V padded
constexpr int M1   = 512;             // 456 G rows + 24 Jreg rows + pad
constexpr int N1   = 768;             // 621 posedirs + 30 shapedirs + 3 tpl + 1 ones + pad
constexpr int SPLITK1 = 12;           // 6912/12 = 576 = 18*32
constexpr int KSEG = VP / SPLITK1;    // 576
constexpr int KQ   = 256;             // 1 + 10 + 207 = 218, padded to 256
constexpr int N2   = 1408;            // 456*3 = 1368, padded
constexpr int SPLITK2 = 2;            // 256/2 = 128 = 4*32
constexpr int PSTR = B * N2;

// bf16 hi/lo split operands
__device__ __align__(256) __nv_bfloat16 g_Gh[M1 * VP];
__device__ __align__(256) __nv_bfloat16 g_Gl[M1 * VP];
__device__ __align__(256) __nv_bfloat16 g_Eh[N1 * VP];
__device__ __align__(256) __nv_bfloat16 g_El[N1 * VP];
__device__ __align__(256) __nv_bfloat16 g_A2h[KQ * B];
__device__ __align__(256) __nv_bfloat16 g_A2l[KQ * B];
__device__ __align__(256) __nv_bfloat16 g_CTh[KQ * N2];
__device__ __align__(256) __nv_bfloat16 g_CTl[KQ * N2];

__device__ __align__(256) float g_Cp [SPLITK1 * M1 * N1];
__device__ __align__(256) float g_S  [456];
__device__ __align__(256) float g_JT [24 * 33];
__device__ __align__(256) float g_Rg [B * 288];
__device__ __align__(256) float g_P  [SPLITK2 * B * N2];

__constant__ int c_par[24] = {-1,0,0,0,1,2,3,4,5,6,7,8,9,9,9,12,13,14,16,17,18,19,20,21};

__device__ __forceinline__ void split_bf16(float val, __nv_bfloat16& hi,
                                           __nv_bfloat16& lo) {
    hi = __float2bfloat16(val);
    lo = __float2bfloat16(val - __bfloat162float(hi));
}

// ---------------------------------------------------------------------------
// buildEt pose rows: n = 3p+c for p = blockIdx.y. 128 thr, 2 v per thread.
// ---------------------------------------------------------------------------
__global__ void k_buildEt_pose(const float* __restrict__ posedirs) {
    const int p  = blockIdx.y;
    const int vv = (blockIdx.x * 128 + threadIdx.x) * 2;
    const float* src = posedirs + (size_t)p * (V * 3) + 3 * vv;
    float f[6] = {0, 0, 0, 0, 0, 0};
    if (vv + 1 < V) {
#pragma unroll
        for (int i = 0; i < 6; ++i) f[i] = src[i];
    } else if (vv < V) {
#pragma unroll
        for (int i = 0; i < 3; ++i) f[i] = src[i];
    }
#pragma unroll
    for (int c = 0; c < 3; ++c) {
        __nv_bfloat16 h0, l0, h1, l1;
        split_bf16(f[c], h0, l0);
        split_bf16(f[3 + c], h1, l1);
        size_t off = (size_t)(3 * p + c) * VP + vv;
        *(__nv_bfloat162*)(g_Eh + off) = __nv_bfloat162(h0, h1);
        *(__nv_bfloat162*)(g_El + off) = __nv_bfloat162(l0, l1);
    }
}

// ---------------------------------------------------------------------------
// buildEt rest rows: n = 621 + blockIdx.y (147 rows).
// ---------------------------------------------------------------------------
__global__ void k_buildEt_rest(const float* __restrict__ shapedirs,
                               const float* __restrict__ v_template) {
    const int n  = 621 + blockIdx.y;
    const int vv = (blockIdx.x * 128 + threadIdx.x) * 2;
    float f0 = 0.f, f1 = 0.f;
    if (n < 651) {
        int t = n - 621, q = t / 3, c = t - 3 * q;      // uniform
        const float* src = shapedirs + (size_t)q * (V * 3);
        if (vv < V)     f0 = src[3 * vv + c];
        if (vv + 1 < V) f1 = src[3 * (vv + 1) + c];
    } else if (n < 654) {
        int c = n - 651;
        if (vv < V)     f0 = v_template[3 * vv + c];
        if (vv + 1 < V) f1 = v_template[3 * (vv + 1) + c];
    } else if (n == 654) {
        if (vv < V)     f0 = 1.f;
        if (vv + 1 < V) f1 = 1.f;
    }
    __nv_bfloat16 h0, l0, h1, l1;
    split_bf16(f0, h0, l0);
    split_bf16(f1, h1, l1);
    size_t off = (size_t)n * VP + vv;
    *(__nv_bfloat162*)(g_Eh + off) = __nv_bfloat162(h0, h1);
    *(__nv_bfloat162*)(g_El + off) = __nv_bfloat162(l0, l1);
}

// ---------------------------------------------------------------------------
// buildGt: row m = blockIdx.y; 192 threads, 4 v per thread.
// ---------------------------------------------------------------------------
__global__ void k_buildGt(const float* __restrict__ jr19,
                          const float* __restrict__ w24,
                          const float* __restrict__ Jreg24) {
    const int m  = blockIdx.y;
    const int v0 = (blockIdx.x * 192 + threadIdx.x) * 4;
    float f[4] = {0, 0, 0, 0};
    if (m < 456) {
        int k = m / 24, j = m - 24 * (m / 24);          // uniform
#pragma unroll
        for (int i = 0; i < 4; ++i) {
            int v = v0 + i;
            if (v < V) f[i] = jr19[v * NK + k] * w24[v * NJ + j];
        }
    } else if (m < 480) {
        int j = m - 456;                                 // uniform
#pragma unroll
        for (int i = 0; i < 4; ++i) {
            int v = v0 + i;
            if (v < V) f[i] = Jreg24[v * NJ + j];
        }
    }
    __nv_bfloat16 h[4], l[4];
#pragma unroll
    for (int i = 0; i < 4; ++i) split_bf16(f[i], h[i], l[i]);
    size_t off = (size_t)m * VP + v0;
    *(__nv_bfloat162*)(g_Gh + off)     = __nv_bfloat162(h[0], h[1]);
    *(__nv_bfloat162*)(g_Gh + off + 2) = __nv_bfloat162(h[2], h[3]);
    *(__nv_bfloat162*)(g_Gl + off)     = __nv_bfloat162(l[0], l[1]);
    *(__nv_bfloat162*)(g_Gl + off + 2) = __nv_bfloat162(l[2], l[3]);
}

// ---------------------------------------------------------------------------
// GEMM1 on WMMA bf16x3: C[m][n] = sum_v G[m,v]*E[n,v].
// CTA 128x128, BK=32, 8 warps (2m x 4n), 64x32 per warp, 2 CTAs/SM.
// ---------------------------------------------------------------------------
__global__ void __launch_bounds__(256, 2) k_gemm1_wmma() {
    using namespace nvcuda;

    __shared__ __align__(16) __nv_bfloat16 Ah[128][40];
    __shared__ __align__(16) __nv_bfloat16 Al[128][40];
    __shared__ __align__(16) __nv_bfloat16 Bh[128][40];
    __shared__ __align__(16) __nv_bfloat16 Bl[128][40];

    const int n0    = blockIdx.x * 128;
    const int m0    = blockIdx.y * 128;
    const int split = blockIdx.z;
    const int tid   = threadIdx.x;
    const int wid   = tid >> 5;
    const int wm    = (wid & 1) * 64;
    const int wn    = (wid >> 1) * 32;

    wmma::fragment<wmma::accumulator, 16, 16, 16, float> acc[4][2];
#pragma unroll
    for (int i = 0; i < 4; ++i)
#pragma unroll
        for (int j = 0; j < 2; ++j)
            wmma::fill_fragment(acc[i][j], 0.f);

    const int kbase = split * KSEG;
    const int nIter = KSEG / 32;          // 18

    uint4 pAh[2], pAl[2], pBh[2], pBl[2];
#pragma unroll
    for (int i = 0; i < 2; ++i) {
        int linear = tid + 256 * i;
        int r = linear >> 2, c = (linear & 3) * 8;
        pAh[i] = *(const uint4*)(g_Gh + (size_t)(m0 + r) * VP + kbase + c);
        pAl[i] = *(const uint4*)(g_Gl + (size_t)(m0 + r) * VP + kbase + c);
        pBh[i] = *(const uint4*)(g_Eh + (size_t)(n0 + r) * VP + kbase + c);
        pBl[i] = *(const uint4*)(g_El + (size_t)(n0 + r) * VP + kbase + c);
    }

    for (int it = 0; it < nIter; ++it) {
        __syncthreads();
#pragma unroll
        for (int i = 0; i < 2; ++i) {
            int linear = tid + 256 * i;
            int r = linear >> 2, c = (linear & 3) * 8;
            *(uint4*)&Ah[r][c] = pAh[i];
            *(uint4*)&Al[r][c] = pAl[i];
            *(uint4*)&Bh[r][c] = pBh[i];
            *(uint4*)&Bl[r][c] = pBl[i];
        }
        __syncthreads();
        if (it + 1 < nIter) {
            int kk = kbase + (it + 1) * 32;
#pragma unroll
            for (int i = 0; i < 2; ++i) {
                int linear = tid + 256 * i;
                int r = linear >> 2, c = (linear & 3) * 8;
                pAh[i] = *(const uint4*)(g_Gh + (size_t)(m0 + r) * VP + kk + c);
                pAl[i] = *(const uint4*)(g_Gl + (size_t)(m0 + r) * VP + kk + c);
                pBh[i] = *(const uint4*)(g_Eh + (size_t)(n0 + r) * VP + kk + c);
                pBl[i] = *(const uint4*)(g_El + (size_t)(n0 + r) * VP + kk + c);
            }
        }
#pragma unroll
        for (int k0 = 0; k0 < 32; k0 += 16) {
            wmma::fragment<wmma::matrix_a, 16, 16, 16, __nv_bfloat16,
                           wmma::row_major> ah[4], al[4];
            wmma::fragment<wmma::matrix_b, 16, 16, 16, __nv_bfloat16,
                           wmma::col_major> bh[2], bl[2];
#pragma unroll
            for (int i = 0; i < 4; ++i) {
                wmma::load_matrix_sync(ah[i], &Ah[wm + i * 16][k0], 40);
                wmma::load_matrix_sync(al[i], &Al[wm + i * 16][k0], 40);
            }
#pragma unroll
            for (int j = 0; j < 2; ++j) {
                wmma::load_matrix_sync(bh[j], &Bh[wn + j * 16][k0], 40);
                wmma::load_matrix_sync(bl[j], &Bl[wn + j * 16][k0], 40);
            }
#pragma unroll
            for (int i = 0; i < 4; ++i)
#pragma unroll
                for (int j = 0; j < 2; ++j) {
                    wmma::mma_sync(acc[i][j], ah[i], bh[j], acc[i][j]);
                    wmma::mma_sync(acc[i][j], al[i], bh[j], acc[i][j]);
                    wmma::mma_sync(acc[i][j], ah[i], bl[j], acc[i][j]);
                }
        }
    }

    float* Co = g_Cp + (size_t)split * (M1 * N1);
#pragma unroll
    for (int i = 0; i < 4; ++i)
#pragma unroll
        for (int j = 0; j < 2; ++j)
            wmma::store_matrix_sync(
                &Co[(size_t)(m0 + wm + i * 16) * N1 + n0 + wn + j * 16],
                acc[i][j], N1, wmma::mem_row_major);
}

// ---------------------------------------------------------------------------
// GEMM2 on WMMA bf16x3: P[b][n] = sum_q A2[b,q]*CT[q,n].
// A2 staged K-major [q][b] (matrix_a col_major), CT [q][n] (matrix_b row_major).
// CTA 128x128, BK=32, 8 warps, split-K=2.
// ---------------------------------------------------------------------------
__global__ void __launch_bounds__(256, 2) k_gemm2_wmma() {
    using namespace nvcuda;

    __shared__ __align__(16) __nv_bfloat16 Ah[32][136];
    __shared__ __align__(16) __nv_bfloat16 Al[32][136];
    __shared__ __align__(16) __nv_bfloat16 Bh[32][136];
    __shared__ __align__(16) __nv_bfloat16 Bl[32][136];

    const int n0    = blockIdx.x * 128;
    const int m0    = blockIdx.y * 128;   // batch dim
    const int split = blockIdx.z;
    const int tid   = threadIdx.x;
    const int wid   = tid >> 5;
    const int wm    = (wid & 1) * 64;
    const int wn    = (wid >> 1) * 32;

    wmma::fragment<wmma::accumulator, 16, 16, 16, float> acc[4][2];
#pragma unroll
    for (int i = 0; i < 4; ++i)
#pragma unroll
        for (int j = 0; j < 2; ++j)
            wmma::fill_fragment(acc[i][j], 0.f);

    const int kbase = split * (KQ / SPLITK2);
    const int nIter = (KQ / SPLITK2) / 32;   // 4

    uint4 pAh[2], pAl[2], pBh[2], pBl[2];
#pragma unroll
    for (int i = 0; i < 2; ++i) {
        int linear = tid + 256 * i;
        int r = linear >> 4, c = (linear & 15) * 8;
        pAh[i] = *(const uint4*)(g_A2h + (size_t)(kbase + r) * B + m0 + c);
        pAl[i] = *(const uint4*)(g_A2l + (size_t)(kbase + r) * B + m0 + c);
        pBh[i] = *(const uint4*)(g_CTh + (size_t)(kbase + r) * N2 + n0 + c);
        pBl[i] = *(const uint4*)(g_CTl + (size_t)(kbase + r) * N2 + n0 + c);
    }

    for (int it = 0; it < nIter; ++it) {
        __syncthreads();
#pragma unroll
        for (int i = 0; i < 2; ++i) {
            int linear = tid + 256 * i;
            int r = linear >> 4, c = (linear & 15) * 8;
            *(uint4*)&Ah[r][c] = pAh[i];
            *(uint4*)&Al[r][c] = pAl[i];
            *(uint4*)&Bh[r][c] = pBh[i];
            *(uint4*)&Bl[r][c] = pBl[i];
        }
        __syncthreads();
        if (it + 1 < nIter) {
            int kk = kbase + (it + 1) * 32;
#pragma unroll
            for (int i = 0; i < 2; ++i) {
                int linear = tid + 256 * i;
                int r = linear >> 4, c = (linear & 15) * 8;
                pAh[i] = *(const uint4*)(g_A2h + (size_t)(kk + r) * B + m0 + c);
                pAl[i] = *(const uint4*)(g_A2l + (size_t)(kk + r) * B + m0 + c);
                pBh[i] = *(const uint4*)(g_CTh + (size_t)(kk + r) * N2 + n0 + c);
                pBl[i] = *(const uint4*)(g_CTl + (size_t)(kk + r) * N2 + n0 + c);
            }
        }
#pragma unroll
        for (int k0 = 0; k0 < 32; k0 += 16) {
            wmma::fragment<wmma::matrix_a, 16, 16, 16, __nv_bfloat16,
                           wmma::col_major> ah[4], al[4];
            wmma::fragment<wmma::matrix_b, 16, 16, 16, __nv_bfloat16,
                           wmma::row_major> bh[2], bl[2];
#pragma unroll
            for (int i = 0; i < 4; ++i) {
                wmma::load_matrix_sync(ah[i], &Ah[k0][wm + i * 16], 136);
                wmma::load_matrix_sync(al[i], &Al[k0][wm + i * 16], 136);
            }
#pragma unroll
            for (int j = 0; j < 2; ++j) {
                wmma::load_matrix_sync(bh[j], &Bh[k0][wn + j * 16], 136);
                wmma::load_matrix_sync(bl[j], &Bl[k0][wn + j * 16], 136);
            }
#pragma unroll
            for (int i = 0; i < 4; ++i)
#pragma unroll
                for (int j = 0; j < 2; ++j) {
                    wmma::mma_sync(acc[i][j], ah[i], bh[j], acc[i][j]);
                    wmma::mma_sync(acc[i][j], al[i], bh[j], acc[i][j]);
                    wmma::mma_sync(acc[i][j], ah[i], bl[j], acc[i][j]);
                }
        }
    }

    float* Po = g_P + (size_t)split * PSTR;
#pragma unroll
    for (int i = 0; i < 4; ++i)
#pragma unroll
        for (int j = 0; j < 2; ++j)
            wmma::store_matrix_sync(
                &Po[(size_t)(m0 + wm + i * 16) * N2 + n0 + wn + j * 16],
                acc[i][j], N2, wmma::mem_row_major);
}

// ---------------------------------------------------------------------------
// Reduce GEMM1 split-K partials into CTh/CTl (bf16), S, JT.
// ---------------------------------------------------------------------------
__global__ void k_reduce() {
    int idx = blockIdx.x * blockDim.x + threadIdx.x;
    const int NCT = KQ * N2;
    if (idx < NCT) {
        int q = idx / N2, m = idx - q * N2;
        float val = 0.f;
        if (m < 1368 && q < 218) {
            int kj = m / 3, c = m - 3 * kj;
            int col;
            if (q == 0)        col = 651 + c;
            else if (q <= 10)  col = 621 + (q - 1) * 3 + c;
            else               col = (q - 11) * 3 + c;
            size_t off = (size_t)kj * N1 + col;
#pragma unroll
            for (int s = 0; s < SPLITK1; ++s)
                val += g_Cp[(size_t)s * (M1 * N1) + off];
        }
        __nv_bfloat16 hi, lo;
        split_bf16(val, hi, lo);
        g_CTh[idx] = hi;
        g_CTl[idx] = lo;
    } else if (idx < NCT + 456) {
        int kj = idx - NCT;
        float val = 0.f;
#pragma unroll
        for (int s = 0; s < SPLITK1; ++s)
            val += g_Cp[(size_t)s * (M1 * N1) + (size_t)kj * N1 + 654];
        g_S[kj] = val;
    } else if (idx < NCT + 456 + 24 * 33) {
        int t2 = idx - NCT - 456;
        int j = t2 / 33, t = t2 - 33 * j;
        float val = 0.f;
#pragma unroll
        for (int s = 0; s < SPLITK1; ++s)
            val += g_Cp[(size_t)s * (M1 * N1) + (size_t)(456 + j) * N1 + 621 + t];
        g_JT[t2] = val;
    }
}

// ---------------------------------------------------------------------------
// Per-body prep (one warp / body). Emits A2 column as bf16 hi/lo.
// ---------------------------------------------------------------------------
__global__ void k_prep(const float* __restrict__ beta,
                       const float* __restrict__ theta) {
    const int b = blockIdx.x;
    const int lane = threadIdx.x;

    __shared__ float Rsm[24][9];
    __shared__ float Jm[24][3];
    __shared__ float Ag[24][12];
    __shared__ float bet[10];

    if (lane < 10) bet[lane] = beta[b * NB + lane];
    __syncwarp();

    if (lane < 24) {
        float tx = theta[b * 72 + lane * 3 + 0];
        float ty = theta[b * 72 + lane * 3 + 1];
        float tz = theta[b * 72 + lane * 3 + 2];
        float ax = tx + 1e-8f, ay = ty + 1e-8f, az = tz + 1e-8f;
        float angle = sqrtf(ax * ax + ay * ay + az * az);
        float half = 0.5f * angle;
        float s = sinf(half), cw = cosf(half);
        float vx = tx / angle * s, vy = ty / angle * s, vz = tz / angle * s;
        float qn = sqrtf(cw * cw + vx * vx + vy * vy + vz * vz);
        float w = cw / qn, x = vx / qn, y = vy / qn, z = vz / qn;
        Rsm[lane][0] = 1.f - 2.f * (y * y + z * z);
        Rsm[lane][1] = 2.f * (x * y - w * z);
        Rsm[lane][2] = 2.f * (x * z + w * y);
        Rsm[lane][3] = 2.f * (x * y + w * z);
        Rsm[lane][4] = 1.f - 2.f * (x * x + z * z);
        Rsm[lane][5] = 2.f * (y * z - w * x);
        Rsm[lane][6] = 2.f * (x * z - w * y);
        Rsm[lane][7] = 2.f * (y * z + w * x);
        Rsm[lane][8] = 1.f - 2.f * (x * x + y * y);
#pragma unroll
        for (int c = 0; c < 3; ++c) {
            float val = g_JT[lane * 33 + 30 + c];
#pragma unroll
            for (int n = 0; n < 10; ++n)
                val += bet[n] * g_JT[lane * 33 + n * 3 + c];
            Jm[lane][c] = val;
        }
    }
    __syncwarp();

    for (int q = lane; q < KQ; q += 32) {
        float val;
        if (q == 0) val = 1.f;
        else if (q <= 10) val = bet[q - 1];
        else if (q < 218) {
            int p = q - 11;
            int i = p / 9 + 1, e = p - 9 * (p / 9);
            val = Rsm[i][e] - ((e == 0 || e == 4 || e == 8) ? 1.f : 0.f);
        } else val = 0.f;
        __nv_bfloat16 hi, lo;
        split_bf16(val, hi, lo);
        g_A2h[q * B + b] = hi;
        g_A2l[q * B + b] = lo;
    }

    const int r = lane >> 2, cc = lane & 3;
    for (int i = 0; i < 24; ++i) {
        if (lane < 12) {
            float val;
            if (i == 0) {
                val = (cc < 3) ? Rsm[0][r * 3 + cc] * (cc == 0 ? 1.f : -1.f)
                               : Jm[0][r];
            } else {
                int par = c_par[i];
                float l0, l1, l2;
                if (cc < 3) {
                    l0 = Rsm[i][0 * 3 + cc];
                    l1 = Rsm[i][1 * 3 + cc];
                    l2 = Rsm[i][2 * 3 + cc];
                } else {
                    l0 = Jm[i][0] - Jm[par][0];
                    l1 = Jm[i][1] - Jm[par][1];
                    l2 = Jm[i][2] - Jm[par][2];
                }
                val = Ag[par][r * 4 + 0] * l0 + Ag[par][r * 4 + 1] * l1 +
                      Ag[par][r * 4 + 2] * l2;
                if (cc == 3) val += Ag[par][r * 4 + 3];
            }
            Ag[i][r * 4 + cc] = val;
        }
        __syncwarp();
    }

    for (int idx = lane; idx < 288; idx += 32) {
        int j = idx / 12, e = idx - 12 * j;
        float out;
        if (e < 9) {
            int rr = e / 3, c = e - 3 * rr;
            out = Ag[j][rr * 4 + c];
        } else {
            int rr = e - 9;
            out = Ag[j][rr * 4 + 3] -
                  (Ag[j][rr * 4 + 0] * Jm[j][0] + Ag[j][rr * 4 + 1] * Jm[j][1] +
                   Ag[j][rr * 4 + 2] * Jm[j][2]);
        }
        g_Rg[b * 288 + idx] = out;
    }
}

// ---------------------------------------------------------------------------
// joints epilogue (folds 2 GEMM2 split-K partials)
// ---------------------------------------------------------------------------
__global__ void k_joints(const float* __restrict__ trans,
                         float* __restrict__ out) {
    const int b = blockIdx.x;
    const int tid = threadIdx.x;
    __shared__ float sA[288];
    __shared__ float sS[456];
    for (int i = tid; i < 288; i += 64) sA[i] = g_Rg[b * 288 + i];
    for (int i = tid; i < 456; i += 64) sS[i] = g_S[i];
    __syncthreads();
    if (tid < 57) {
        int k = tid / 3, r = tid - 3 * k;
        float acc = trans[b * 3 + r];
        const float* Pb0 = &g_P[(size_t)b * N2];
        const float* Pb1 = &g_P[(size_t)PSTR + (size_t)b * N2];
#pragma unroll
        for (int j = 0; j < 24; ++j) {
            const float* M = &sA[j * 12];
            int m = (k * 24 + j) * 3;
            float p0 = Pb0[m + 0] + Pb1[m + 0];
            float p1 = Pb0[m + 1] + Pb1[m + 1];
            float p2 = Pb0[m + 2] + Pb1[m + 2];
            acc += M[r * 3 + 0] * p0 + M[r * 3 + 1] * p1 + M[r * 3 + 2] * p2 +
                   M[9 + r] * sS[k * 24 + j];
        }
        out[b * 57 + tid] = acc;
    }
}

} // namespace smpl

extern "C" void kernel_launch(void* const* d_in, const int* in_sizes, int n_in,
                              void* d_out, int out_size) {
    using namespace smpl;
    const float* beta       = (const float*)d_in[0];
    const float* theta      = (const float*)d_in[1];
    const float* trans      = (const float*)d_in[2];
    const float* v_template = (const float*)d_in[3];
    const float* shapedirs  = (const float*)d_in[4];
    const float* J_reg      = (const float*)d_in[5];
    const float* posedirs   = (const float*)d_in[6];
    const float* joint_reg  = (const float*)d_in[7];
    const float* weights    = (const float*)d_in[8];
    float* out = (float*)d_out;

    // 1) Build bf16 hi/lo operands
    {
        dim3 grid(VP / 256, 207);                 // 27 x 207, 2 v/thread
        k_buildEt_pose<<<grid, 128>>>(posedirs);
    }
    {
        dim3 grid(VP / 256, 147);                 // 27 x 147
        k_buildEt_rest<<<grid, 128>>>(shapedirs, v_template);
    }
    {
        dim3 grid(VP / 768, M1);                  // 9 x 512, 4 v/thread
        k_buildGt<<<grid, 192>>>(joint_reg, weights, J_reg);
    }

    // 2) GEMM1 on WMMA bf16x3, split-K = 12
    {
        dim3 grid(N1 / 128, M1 / 128, SPLITK1);   // 6 x 4 x 12 = 288 CTAs
        k_gemm1_wmma<<<grid, 256>>>();
    }

    // 3) Reduce partials -> CTh/CTl / S / JT
    {
        int n = KQ * N2 + 456 + 24 * 33;
        k_reduce<<<(n + 255) / 256, 256>>>();
    }

    // 4) Per-body prep
    k_prep<<<B, 32>>>(beta, theta);

    // 5) GEMM2 on WMMA bf16x3, split-K = 2
    {
        dim3 grid(N2 / 128, B / 128, SPLITK2);    // 11 x 8 x 2 = 176 CTAs
        k_gemm2_wmma<<<grid, 256>>>();
    }

    // 6) Joints epilogue
    k_joints<<<B, 64>>>(trans, out);
}

// round 6
// speedup vs baseline: 1.5065x; 1.5065x over previous
#include <cuda_runtime.h>
#include <cuda_bf16.h>
#include <cuda_fp16.h>
#include <mma.h>
#include <cstdint>

// ---------------------------------------------------------------------------
// SMPL fused pipeline, round 6: GEMM1 fp16 2-term (L1-traffic diet),
// double-buffered smem, coalesced builds via transposed regressors.
// ---------------------------------------------------------------------------

namespace smpl {

constexpr int V    = 6890;
constexpr int NB   = 10;
constexpr int NJ   = 24;
constexpr int NK   = 19;
constexpr int B    = 1024;

constexpr int VP   = 6912;
constexpr int M1   = 512;
constexpr int N1   = 768;
constexpr int SPLITK1 = 12;           // KSEG = 576 = 18*32
constexpr int KSEG = VP / SPLITK1;
constexpr int KQ   = 256;             // 218 padded
constexpr int N2   = 1408;            // 1368 padded
constexpr int SPLITK2 = 2;
constexpr int PSTR = B * N2;

// GEMM1 fp16 operands (K = v contiguous)
__device__ __align__(256) __half g_Gh16[M1 * VP];
__device__ __align__(256) __half g_Gl16[M1 * VP];
__device__ __align__(256) __half g_Eh16[N1 * VP];

// transposed regressors [c][v]
__device__ __align__(256) float g_jrT [NK * VP];
__device__ __align__(256) float g_wT  [NJ * VP];
__device__ __align__(256) float g_JregT[NJ * VP];

// GEMM2 bf16 operands
__device__ __align__(256) __nv_bfloat16 g_A2h[KQ * B];
__device__ __align__(256) __nv_bfloat16 g_A2l[KQ * B];
__device__ __align__(256) __nv_bfloat16 g_CTh[KQ * N2];
__device__ __align__(256) __nv_bfloat16 g_CTl[KQ * N2];

__device__ __align__(256) float g_Cp [SPLITK1 * M1 * N1];
__device__ __align__(256) float g_S  [456];
__device__ __align__(256) float g_JT [24 * 33];
__device__ __align__(256) float g_Rg [B * 288];
__device__ __align__(256) float g_P  [SPLITK2 * B * N2];

__constant__ int c_par[24] = {-1,0,0,0,1,2,3,4,5,6,7,8,9,9,9,12,13,14,16,17,18,19,20,21};

__device__ __forceinline__ void split_h16(float v, __half& hi, __half& lo) {
    hi = __float2half_rn(v);
    lo = __float2half_rn(v - __half2float(hi));
}
__device__ __forceinline__ void split_bf16(float val, __nv_bfloat16& hi,
                                           __nv_bfloat16& lo) {
    hi = __float2bfloat16(val);
    lo = __float2bfloat16(val - __bfloat162float(hi));
}

// ---------------------------------------------------------------------------
// transpose: out[c][v] = in[v][c], c = blockIdx.y
// ---------------------------------------------------------------------------
__global__ void k_transpose(const float* __restrict__ in,
                            float* __restrict__ out, int C) {
    int v = blockIdx.x * 256 + threadIdx.x;
    int c = blockIdx.y;
    out[(size_t)c * VP + v] = (v < V) ? in[(size_t)v * C + c] : 0.f;
}

// ---------------------------------------------------------------------------
// buildEh: pose rows (fp16 single). p = blockIdx.y, 2 v per thread.
// ---------------------------------------------------------------------------
__global__ void k_buildEh_pose(const float* __restrict__ posedirs) {
    const int p  = blockIdx.y;
    const int vv = (blockIdx.x * 128 + threadIdx.x) * 2;
    const float* src = posedirs + (size_t)p * (V * 3) + 3 * vv;
    float f[6] = {0, 0, 0, 0, 0, 0};
    if (vv + 1 < V) {
#pragma unroll
        for (int i = 0; i < 6; ++i) f[i] = src[i];
    } else if (vv < V) {
#pragma unroll
        for (int i = 0; i < 3; ++i) f[i] = src[i];
    }
#pragma unroll
    for (int c = 0; c < 3; ++c) {
        __half2 h = __floats2half2_rn(f[c], f[3 + c]);
        *(__half2*)(g_Eh16 + (size_t)(3 * p + c) * VP + vv) = h;
    }
}

// ---------------------------------------------------------------------------
// buildEh rest rows: n = 621 + blockIdx.y (147 rows incl pad)
// ---------------------------------------------------------------------------
__global__ void k_buildEh_rest(const float* __restrict__ shapedirs,
                               const float* __restrict__ v_template) {
    const int n  = 621 + blockIdx.y;
    const int vv = (blockIdx.x * 128 + threadIdx.x) * 2;
    float f0 = 0.f, f1 = 0.f;
    if (n < 651) {
        int t = n - 621, q = t / 3, c = t - 3 * q;   // uniform
        const float* src = shapedirs + (size_t)q * (V * 3);
        if (vv < V)     f0 = src[3 * vv + c];
        if (vv + 1 < V) f1 = src[3 * (vv + 1) + c];
    } else if (n < 654) {
        int c = n - 651;
        if (vv < V)     f0 = v_template[3 * vv + c];
        if (vv + 1 < V) f1 = v_template[3 * (vv + 1) + c];
    } else if (n == 654) {
        if (vv < V)     f0 = 1.f;
        if (vv + 1 < V) f1 = 1.f;
    }
    *(__half2*)(g_Eh16 + (size_t)n * VP + vv) = __floats2half2_rn(f0, f1);
}

// ---------------------------------------------------------------------------
// buildGt: m = blockIdx.y, 4 v per thread, fully coalesced via transposes.
// ---------------------------------------------------------------------------
__global__ void k_buildGt(/* no args */) {
    const int m  = blockIdx.y;
    const int v0 = (blockIdx.x * 256 + threadIdx.x) * 4;
    if (v0 >= VP) return;
    float4 f = make_float4(0.f, 0.f, 0.f, 0.f);
    if (m < 456) {
        int k = m / 24, j = m - 24 * (m / 24);       // uniform per row
        float4 a = *(const float4*)(g_jrT + (size_t)k * VP + v0);
        float4 b = *(const float4*)(g_wT  + (size_t)j * VP + v0);
        f = make_float4(a.x * b.x, a.y * b.y, a.z * b.z, a.w * b.w);
    } else if (m < 480) {
        f = *(const float4*)(g_JregT + (size_t)(m - 456) * VP + v0);
    }
    __half h[4], l[4];
    split_h16(f.x, h[0], l[0]);
    split_h16(f.y, h[1], l[1]);
    split_h16(f.z, h[2], l[2]);
    split_h16(f.w, h[3], l[3]);
    size_t off = (size_t)m * VP + v0;
    *(__half2*)(g_Gh16 + off)     = __half2(h[0], h[1]);
    *(__half2*)(g_Gh16 + off + 2) = __half2(h[2], h[3]);
    *(__half2*)(g_Gl16 + off)     = __half2(l[0], l[1]);
    *(__half2*)(g_Gl16 + off + 2) = __half2(l[2], l[3]);
}

// ---------------------------------------------------------------------------
// GEMM1: C[m][n] = sum_v G[m,v]*E[n,v], fp16 2-term (Gh+Gl)*Eh.
// CTA 128x128, BK=32, 8 warps as 4m x 2n (32x64 per warp),
// double-buffered dynamic smem (60KB), 1 sync/iter, reg prefetch.
// ---------------------------------------------------------------------------
constexpr int G1_PLANE = 128 * 40;                 // halves per plane
constexpr int G1_BUF   = 3 * G1_PLANE;             // halves per buffer
constexpr int G1_SMEM  = 2 * G1_BUF * 2;           // bytes = 61440

__global__ void __launch_bounds__(256, 2) k_gemm1_wmma() {
    using namespace nvcuda;
    extern __shared__ __align__(16) __half dynsmem[];

    const int n0    = blockIdx.x * 128;
    const int m0    = blockIdx.y * 128;
    const int split = blockIdx.z;
    const int tid   = threadIdx.x;
    const int wid   = tid >> 5;
    const int wm    = (wid & 3) * 32;
    const int wn    = (wid >> 2) * 64;

    wmma::fragment<wmma::accumulator, 16, 16, 16, float> acc[2][4];
#pragma unroll
    for (int i = 0; i < 2; ++i)
#pragma unroll
        for (int j = 0; j < 4; ++j)
            wmma::fill_fragment(acc[i][j], 0.f);

    const int kbase = split * KSEG;
    const int nIter = KSEG / 32;                   // 18

    const int r = tid >> 2;                        // 0..63? no: tid/4 -> 0..63
    // each thread stores 16 halves per plane: rows r and r+64
    const int c = (tid & 3) * 8;

    uint4 pAh[2], pAl[2], pBh[2];

    auto ldg_tile = [&](int kk) {
#pragma unroll
        for (int i = 0; i < 2; ++i) {
            int row = r + 64 * i;
            pAh[i] = *(const uint4*)(g_Gh16 + (size_t)(m0 + row) * VP + kk + c);
            pAl[i] = *(const uint4*)(g_Gl16 + (size_t)(m0 + row) * VP + kk + c);
            pBh[i] = *(const uint4*)(g_Eh16 + (size_t)(n0 + row) * VP + kk + c);
        }
    };
    auto sts_tile = [&](int buf) {
        __half* base = dynsmem + buf * G1_BUF;
#pragma unroll
        for (int i = 0; i < 2; ++i) {
            int row = r + 64 * i;
            *(uint4*)(base + row * 40 + c)                 = pAh[i];
            *(uint4*)(base + G1_PLANE + row * 40 + c)      = pAl[i];
            *(uint4*)(base + 2 * G1_PLANE + row * 40 + c)  = pBh[i];
        }
    };

    // prologue: tile0 -> buf0, tile1 -> regs
    ldg_tile(kbase);
    sts_tile(0);
    ldg_tile(kbase + 32);
    __syncthreads();

    for (int it = 0; it < nIter; ++it) {
        const int cur = it & 1;
        if (it + 1 < nIter) sts_tile(1 - cur);
        if (it + 2 < nIter) ldg_tile(kbase + (it + 2) * 32);

        const __half* Ah = dynsmem + cur * G1_BUF;
        const __half* Al = Ah + G1_PLANE;
        const __half* Bh = Ah + 2 * G1_PLANE;
#pragma unroll
        for (int k0 = 0; k0 < 32; k0 += 16) {
            wmma::fragment<wmma::matrix_a, 16, 16, 16, __half,
                           wmma::row_major> ah[2], al[2];
            wmma::fragment<wmma::matrix_b, 16, 16, 16, __half,
                           wmma::col_major> bh[4];
#pragma unroll
            for (int i = 0; i < 2; ++i) {
                wmma::load_matrix_sync(ah[i], Ah + (wm + i * 16) * 40 + k0, 40);
                wmma::load_matrix_sync(al[i], Al + (wm + i * 16) * 40 + k0, 40);
            }
#pragma unroll
            for (int j = 0; j < 4; ++j)
                wmma::load_matrix_sync(bh[j], Bh + (wn + j * 16) * 40 + k0, 40);
#pragma unroll
            for (int i = 0; i < 2; ++i)
#pragma unroll
                for (int j = 0; j < 4; ++j) {
                    wmma::mma_sync(acc[i][j], ah[i], bh[j], acc[i][j]);
                    wmma::mma_sync(acc[i][j], al[i], bh[j], acc[i][j]);
                }
        }
        __syncthreads();
    }

    float* Co = g_Cp + (size_t)split * (M1 * N1);
#pragma unroll
    for (int i = 0; i < 2; ++i)
#pragma unroll
        for (int j = 0; j < 4; ++j)
            wmma::store_matrix_sync(
                &Co[(size_t)(m0 + wm + i * 16) * N1 + n0 + wn + j * 16],
                acc[i][j], N1, wmma::mem_row_major);
}

// ---------------------------------------------------------------------------
// GEMM2 on WMMA bf16x3 (unchanged from R5, proven): P = A2 @ CT.
// ---------------------------------------------------------------------------
__global__ void __launch_bounds__(256, 2) k_gemm2_wmma() {
    using namespace nvcuda;

    __shared__ __align__(16) __nv_bfloat16 Ah[32][136];
    __shared__ __align__(16) __nv_bfloat16 Al[32][136];
    __shared__ __align__(16) __nv_bfloat16 Bh[32][136];
    __shared__ __align__(16) __nv_bfloat16 Bl[32][136];

    const int n0    = blockIdx.x * 128;
    const int m0    = blockIdx.y * 128;
    const int split = blockIdx.z;
    const int tid   = threadIdx.x;
    const int wid   = tid >> 5;
    const int wm    = (wid & 1) * 64;
    const int wn    = (wid >> 1) * 32;

    wmma::fragment<wmma::accumulator, 16, 16, 16, float> acc[4][2];
#pragma unroll
    for (int i = 0; i < 4; ++i)
#pragma unroll
        for (int j = 0; j < 2; ++j)
            wmma::fill_fragment(acc[i][j], 0.f);

    const int kbase = split * (KQ / SPLITK2);
    const int nIter = (KQ / SPLITK2) / 32;   // 4

    uint4 pAh[2], pAl[2], pBh[2], pBl[2];
#pragma unroll
    for (int i = 0; i < 2; ++i) {
        int linear = tid + 256 * i;
        int rr = linear >> 4, cc = (linear & 15) * 8;
        pAh[i] = *(const uint4*)(g_A2h + (size_t)(kbase + rr) * B + m0 + cc);
        pAl[i] = *(const uint4*)(g_A2l + (size_t)(kbase + rr) * B + m0 + cc);
        pBh[i] = *(const uint4*)(g_CTh + (size_t)(kbase + rr) * N2 + n0 + cc);
        pBl[i] = *(const uint4*)(g_CTl + (size_t)(kbase + rr) * N2 + n0 + cc);
    }

    for (int it = 0; it < nIter; ++it) {
        __syncthreads();
#pragma unroll
        for (int i = 0; i < 2; ++i) {
            int linear = tid + 256 * i;
            int rr = linear >> 4, cc = (linear & 15) * 8;
            *(uint4*)&Ah[rr][cc] = pAh[i];
            *(uint4*)&Al[rr][cc] = pAl[i];
            *(uint4*)&Bh[rr][cc] = pBh[i];
            *(uint4*)&Bl[rr][cc] = pBl[i];
        }
        __syncthreads();
        if (it + 1 < nIter) {
            int kk = kbase + (it + 1) * 32;
#pragma unroll
            for (int i = 0; i < 2; ++i) {
                int linear = tid + 256 * i;
                int rr = linear >> 4, cc = (linear & 15) * 8;
                pAh[i] = *(const uint4*)(g_A2h + (size_t)(kk + rr) * B + m0 + cc);
                pAl[i] = *(const uint4*)(g_A2l + (size_t)(kk + rr) * B + m0 + cc);
                pBh[i] = *(const uint4*)(g_CTh + (size_t)(kk + rr) * N2 + n0 + cc);
                pBl[i] = *(const uint4*)(g_CTl + (size_t)(kk + rr) * N2 + n0 + cc);
            }
        }
#pragma unroll
        for (int k0 = 0; k0 < 32; k0 += 16) {
            wmma::fragment<wmma::matrix_a, 16, 16, 16, __nv_bfloat16,
                           wmma::col_major> ah[4], al[4];
            wmma::fragment<wmma::matrix_b, 16, 16, 16, __nv_bfloat16,
                           wmma::row_major> bh[2], bl[2];
#pragma unroll
            for (int i = 0; i < 4; ++i) {
                wmma::load_matrix_sync(ah[i], &Ah[k0][wm + i * 16], 136);
                wmma::load_matrix_sync(al[i], &Al[k0][wm + i * 16], 136);
            }
#pragma unroll
            for (int j = 0; j < 2; ++j) {
                wmma::load_matrix_sync(bh[j], &Bh[k0][wn + j * 16], 136);
                wmma::load_matrix_sync(bl[j], &Bl[k0][wn + j * 16], 136);
            }
#pragma unroll
            for (int i = 0; i < 4; ++i)
#pragma unroll
                for (int j = 0; j < 2; ++j) {
                    wmma::mma_sync(acc[i][j], ah[i], bh[j], acc[i][j]);
                    wmma::mma_sync(acc[i][j], al[i], bh[j], acc[i][j]);
                    wmma::mma_sync(acc[i][j], ah[i], bl[j], acc[i][j]);
                }
        }
    }

    float* Po = g_P + (size_t)split * PSTR;
#pragma unroll
    for (int i = 0; i < 4; ++i)
#pragma unroll
        for (int j = 0; j < 2; ++j)
            wmma::store_matrix_sync(
                &Po[(size_t)(m0 + wm + i * 16) * N2 + n0 + wn + j * 16],
                acc[i][j], N2, wmma::mem_row_major);
}

// ---------------------------------------------------------------------------
// Reduce GEMM1 split-K partials into CTh/CTl (bf16), S, JT.
// ---------------------------------------------------------------------------
__global__ void k_reduce() {
    int idx = blockIdx.x * blockDim.x + threadIdx.x;
    const int NCT = KQ * N2;
    if (idx < NCT) {
        int q = idx / N2, m = idx - q * N2;
        float val = 0.f;
        if (m < 1368 && q < 218) {
            int kj = m / 3, c = m - 3 * kj;
            int col;
            if (q == 0)        col = 651 + c;
            else if (q <= 10)  col = 621 + (q - 1) * 3 + c;
            else               col = (q - 11) * 3 + c;
            size_t off = (size_t)kj * N1 + col;
#pragma unroll
            for (int s = 0; s < SPLITK1; ++s)
                val += g_Cp[(size_t)s * (M1 * N1) + off];
        }
        __nv_bfloat16 hi, lo;
        split_bf16(val, hi, lo);
        g_CTh[idx] = hi;
        g_CTl[idx] = lo;
    } else if (idx < NCT + 456) {
        int kj = idx - NCT;
        float val = 0.f;
#pragma unroll
        for (int s = 0; s < SPLITK1; ++s)
            val += g_Cp[(size_t)s * (M1 * N1) + (size_t)kj * N1 + 654];
        g_S[kj] = val;
    } else if (idx < NCT + 456 + 24 * 33) {
        int t2 = idx - NCT - 456;
        int j = t2 / 33, t = t2 - 33 * j;
        float val = 0.f;
#pragma unroll
        for (int s = 0; s < SPLITK1; ++s)
            val += g_Cp[(size_t)s * (M1 * N1) + (size_t)(456 + j) * N1 + 621 + t];
        g_JT[t2] = val;
    }
}

// ---------------------------------------------------------------------------
// Per-body prep (one warp / body). Emits A2 column as bf16 hi/lo.
// ---------------------------------------------------------------------------
__global__ void k_prep(const float* __restrict__ beta,
                       const float* __restrict__ theta) {
    const int b = blockIdx.x;
    const int lane = threadIdx.x;

    __shared__ float Rsm[24][9];
    __shared__ float Jm[24][3];
    __shared__ float Ag[24][12];
    __shared__ float bet[10];

    if (lane < 10) bet[lane] = beta[b * NB + lane];
    __syncwarp();

    if (lane < 24) {
        float tx = theta[b * 72 + lane * 3 + 0];
        float ty = theta[b * 72 + lane * 3 + 1];
        float tz = theta[b * 72 + lane * 3 + 2];
        float ax = tx + 1e-8f, ay = ty + 1e-8f, az = tz + 1e-8f;
        float angle = sqrtf(ax * ax + ay * ay + az * az);
        float half = 0.5f * angle;
        float s = sinf(half), cw = cosf(half);
        float vx = tx / angle * s, vy = ty / angle * s, vz = tz / angle * s;
        float qn = sqrtf(cw * cw + vx * vx + vy * vy + vz * vz);
        float w = cw / qn, x = vx / qn, y = vy / qn, z = vz / qn;
        Rsm[lane][0] = 1.f - 2.f * (y * y + z * z);
        Rsm[lane][1] = 2.f * (x * y - w * z);
        Rsm[lane][2] = 2.f * (x * z + w * y);
        Rsm[lane][3] = 2.f * (x * y + w * z);
        Rsm[lane][4] = 1.f - 2.f * (x * x + z * z);
        Rsm[lane][5] = 2.f * (y * z - w * x);
        Rsm[lane][6] = 2.f * (x * z - w * y);
        Rsm[lane][7] = 2.f * (y * z + w * x);
        Rsm[lane][8] = 1.f - 2.f * (x * x + y * y);
#pragma unroll
        for (int c = 0; c < 3; ++c) {
            float val = g_JT[lane * 33 + 30 + c];
#pragma unroll
            for (int n = 0; n < 10; ++n)
                val += bet[n] * g_JT[lane * 33 + n * 3 + c];
            Jm[lane][c] = val;
        }
    }
    __syncwarp();

    for (int q = lane; q < KQ; q += 32) {
        float val;
        if (q == 0) val = 1.f;
        else if (q <= 10) val = bet[q - 1];
        else if (q < 218) {
            int p = q - 11;
            int i = p / 9 + 1, e = p - 9 * (p / 9);
            val = Rsm[i][e] - ((e == 0 || e == 4 || e == 8) ? 1.f : 0.f);
        } else val = 0.f;
        __nv_bfloat16 hi, lo;
        split_bf16(val, hi, lo);
        g_A2h[q * B + b] = hi;
        g_A2l[q * B + b] = lo;
    }

    const int r = lane >> 2, cc = lane & 3;
    for (int i = 0; i < 24; ++i) {
        if (lane < 12) {
            float val;
            if (i == 0) {
                val = (cc < 3) ? Rsm[0][r * 3 + cc] * (cc == 0 ? 1.f : -1.f)
                               : Jm[0][r];
            } else {
                int par = c_par[i];
                float l0, l1, l2;
                if (cc < 3) {
                    l0 = Rsm[i][0 * 3 + cc];
                    l1 = Rsm[i][1 * 3 + cc];
                    l2 = Rsm[i][2 * 3 + cc];
                } else {
                    l0 = Jm[i][0] - Jm[par][0];
                    l1 = Jm[i][1] - Jm[par][1];
                    l2 = Jm[i][2] - Jm[par][2];
                }
                val = Ag[par][r * 4 + 0] * l0 + Ag[par][r * 4 + 1] * l1 +
                      Ag[par][r * 4 + 2] * l2;
                if (cc == 3) val += Ag[par][r * 4 + 3];
            }
            Ag[i][r * 4 + cc] = val;
        }
        __syncwarp();
    }

    for (int idx = lane; idx < 288; idx += 32) {
        int j = idx / 12, e = idx - 12 * j;
        float out;
        if (e < 9) {
            int rr = e / 3, c = e - 3 * rr;
            out = Ag[j][rr * 4 + c];
        } else {
            int rr = e - 9;
            out = Ag[j][rr * 4 + 3] -
                  (Ag[j][rr * 4 + 0] * Jm[j][0] + Ag[j][rr * 4 + 1] * Jm[j][1] +
                   Ag[j][rr * 4 + 2] * Jm[j][2]);
        }
        g_Rg[b * 288 + idx] = out;
    }
}

// ---------------------------------------------------------------------------
// joints epilogue (folds 2 GEMM2 split-K partials)
// ---------------------------------------------------------------------------
__global__ void k_joints(const float* __restrict__ trans,
                         float* __restrict__ out) {
    const int b = blockIdx.x;
    const int tid = threadIdx.x;
    __shared__ float sA[288];
    __shared__ float sS[456];
    for (int i = tid; i < 288; i += 64) sA[i] = g_Rg[b * 288 + i];
    for (int i = tid; i < 456; i += 64) sS[i] = g_S[i];
    __syncthreads();
    if (tid < 57) {
        int k = tid / 3, r = tid - 3 * k;
        float acc = trans[b * 3 + r];
        const float* Pb0 = &g_P[(size_t)b * N2];
        const float* Pb1 = &g_P[(size_t)PSTR + (size_t)b * N2];
#pragma unroll
        for (int j = 0; j < 24; ++j) {
            const float* M = &sA[j * 12];
            int m = (k * 24 + j) * 3;
            float p0 = Pb0[m + 0] + Pb1[m + 0];
            float p1 = Pb0[m + 1] + Pb1[m + 1];
            float p2 = Pb0[m + 2] + Pb1[m + 2];
            acc += M[r * 3 + 0] * p0 + M[r * 3 + 1] * p1 + M[r * 3 + 2] * p2 +
                   M[9 + r] * sS[k * 24 + j];
        }
        out[b * 57 + tid] = acc;
    }
}

} // namespace smpl

extern "C" void kernel_launch(void* const* d_in, const int* in_sizes, int n_in,
                              void* d_out, int out_size) {
    using namespace smpl;
    const float* beta       = (const float*)d_in[0];
    const float* theta      = (const float*)d_in[1];
    const float* trans      = (const float*)d_in[2];
    const float* v_template = (const float*)d_in[3];
    const float* shapedirs  = (const float*)d_in[4];
    const float* J_reg      = (const float*)d_in[5];
    const float* posedirs   = (const float*)d_in[6];
    const float* joint_reg  = (const float*)d_in[7];
    const float* weights    = (const float*)d_in[8];
    float* out = (float*)d_out;

    cudaFuncSetAttribute(k_gemm1_wmma,
                         cudaFuncAttributeMaxDynamicSharedMemorySize, G1_SMEM);

    float *pjrT, *pwT, *pJregT;
    cudaGetSymbolAddress((void**)&pjrT,   g_jrT);
    cudaGetSymbolAddress((void**)&pwT,    g_wT);
    cudaGetSymbolAddress((void**)&pJregT, g_JregT);

    // 0) Transpose regressors -> [c][v]
    {
        dim3 grid(VP / 256, NK);
        k_transpose<<<grid, 256>>>(joint_reg, pjrT, NK);
    }
    {
        dim3 grid(VP / 256, NJ);
        k_transpose<<<grid, 256>>>(weights, pwT, NJ);
    }
    {
        dim3 grid(VP / 256, NJ);
        k_transpose<<<grid, 256>>>(J_reg, pJregT, NJ);
    }

    // 1) Build fp16 operands
    {
        dim3 grid(VP / 256, 207);
        k_buildEh_pose<<<grid, 128>>>(posedirs);
    }
    {
        dim3 grid(VP / 256, 147);
        k_buildEh_rest<<<grid, 128>>>(shapedirs, v_template);
    }
    {
        dim3 grid((VP / 4 + 255) / 256, M1);      // 7 x 512
        k_buildGt<<<grid, 256>>>();
    }

    // 2) GEMM1 fp16 2-term, split-K = 12
    {
        dim3 grid(N1 / 128, M1 / 128, SPLITK1);   // 6 x 4 x 12 = 288 CTAs
        k_gemm1_wmma<<<grid, 256, G1_SMEM>>>();
    }

    // 3) Reduce partials -> CTh/CTl / S / JT
    {
        int n = KQ * N2 + 456 + 24 * 33;
        k_reduce<<<(n + 255) / 256, 256>>>();
    }

    // 4) Per-body prep
    k_prep<<<B, 32>>>(beta, theta);

    // 5) GEMM2 on WMMA bf16x3, split-K = 2
    {
        dim3 grid(N2 / 128, B / 128, SPLITK2);    // 11 x 8 x 2
        k_gemm2_wmma<<<grid, 256>>>();
    }

    // 6) Joints epilogue
    k_joints<<<B, 64>>>(trans, out);
}

// round 7
// speedup vs baseline: 1.8063x; 1.1990x over previous
#include <cuda_runtime.h>
#include <cuda_bf16.h>
#include <cuda_fp16.h>
#include <mma.h>
#include <cstdint>

// ---------------------------------------------------------------------------
// SMPL fused pipeline, round 7: GEMM1 single-term fp16 (half the HMMA work),
// GEMM2 bf16x3, merged transposes, lean builds.
// ---------------------------------------------------------------------------

namespace smpl {

constexpr int V    = 6890;
constexpr int NB   = 10;
constexpr int NJ   = 24;
constexpr int NK   = 19;
constexpr int B    = 1024;

constexpr int VP   = 6912;
constexpr int M1   = 512;
constexpr int N1   = 768;
constexpr int SPLITK1 = 12;           // KSEG = 576 = 18*32
constexpr int KSEG = VP / SPLITK1;
constexpr int KQ   = 256;             // 218 padded
constexpr int N2   = 1408;            // 1368 padded
constexpr int SPLITK2 = 2;
constexpr int PSTR = B * N2;

// GEMM1 fp16 operands (K = v contiguous)
__device__ __align__(256) __half g_Gh16[M1 * VP];
__device__ __align__(256) __half g_Eh16[N1 * VP];

// transposed regressors [c][v]
__device__ __align__(256) float g_jrT  [NK * VP];
__device__ __align__(256) float g_wT   [NJ * VP];
__device__ __align__(256) float g_JregT[NJ * VP];

// GEMM2 bf16 operands
__device__ __align__(256) __nv_bfloat16 g_A2h[KQ * B];
__device__ __align__(256) __nv_bfloat16 g_A2l[KQ * B];
__device__ __align__(256) __nv_bfloat16 g_CTh[KQ * N2];
__device__ __align__(256) __nv_bfloat16 g_CTl[KQ * N2];

__device__ __align__(256) float g_Cp [SPLITK1 * M1 * N1];
__device__ __align__(256) float g_S  [456];
__device__ __align__(256) float g_JT [24 * 33];
__device__ __align__(256) float g_Rg [B * 288];
__device__ __align__(256) float g_P  [SPLITK2 * B * N2];

__constant__ int c_par[24] = {-1,0,0,0,1,2,3,4,5,6,7,8,9,9,9,12,13,14,16,17,18,19,20,21};

__device__ __forceinline__ void split_bf16(float val, __nv_bfloat16& hi,
                                           __nv_bfloat16& lo) {
    hi = __float2bfloat16(val);
    lo = __float2bfloat16(val - __bfloat162float(hi));
}

// ---------------------------------------------------------------------------
// merged transpose: rows [0,NK) -> jrT, [NK,NK+NJ) -> wT, [NK+NJ, ..) -> JregT
// ---------------------------------------------------------------------------
__global__ void k_transpose_all(const float* __restrict__ joint_reg,
                                const float* __restrict__ weights,
                                const float* __restrict__ J_reg) {
    int v = blockIdx.x * 256 + threadIdx.x;
    int row = blockIdx.y;
    const float* in;
    float* out;
    int C, c;
    if (row < NK)           { in = joint_reg; out = g_jrT;   C = NK; c = row; }
    else if (row < NK + NJ) { in = weights;   out = g_wT;    C = NJ; c = row - NK; }
    else                    { in = J_reg;     out = g_JregT; C = NJ; c = row - NK - NJ; }
    out[(size_t)c * VP + v] = (v < V) ? in[(size_t)v * C + c] : 0.f;
}

// ---------------------------------------------------------------------------
// buildEh pose rows: p = blockIdx.y, 2 v per thread, 3 rows per thread.
// ---------------------------------------------------------------------------
__global__ void k_buildEh_pose(const float* __restrict__ posedirs) {
    const int p  = blockIdx.y;
    const int vv = (blockIdx.x * 128 + threadIdx.x) * 2;
    const float* src = posedirs + (size_t)p * (V * 3) + 3 * vv;
    float f[6] = {0, 0, 0, 0, 0, 0};
    if (vv + 1 < V) {
#pragma unroll
        for (int i = 0; i < 6; ++i) f[i] = src[i];
    } else if (vv < V) {
#pragma unroll
        for (int i = 0; i < 3; ++i) f[i] = src[i];
    }
#pragma unroll
    for (int c = 0; c < 3; ++c)
        *(__half2*)(g_Eh16 + (size_t)(3 * p + c) * VP + vv) =
            __floats2half2_rn(f[c], f[3 + c]);
}

// ---------------------------------------------------------------------------
// buildEh rest rows: n = 621 + blockIdx.y (147 rows incl pad)
// ---------------------------------------------------------------------------
__global__ void k_buildEh_rest(const float* __restrict__ shapedirs,
                               const float* __restrict__ v_template) {
    const int n  = 621 + blockIdx.y;
    const int vv = (blockIdx.x * 128 + threadIdx.x) * 2;
    float f0 = 0.f, f1 = 0.f;
    if (n < 651) {
        int t = n - 621, q = t / 3, c = t - 3 * q;   // uniform
        const float* src = shapedirs + (size_t)q * (V * 3);
        if (vv < V)     f0 = src[3 * vv + c];
        if (vv + 1 < V) f1 = src[3 * (vv + 1) + c];
    } else if (n < 654) {
        int c = n - 651;
        if (vv < V)     f0 = v_template[3 * vv + c];
        if (vv + 1 < V) f1 = v_template[3 * (vv + 1) + c];
    } else if (n == 654) {
        if (vv < V)     f0 = 1.f;
        if (vv + 1 < V) f1 = 1.f;
    }
    *(__half2*)(g_Eh16 + (size_t)n * VP + vv) = __floats2half2_rn(f0, f1);
}

// ---------------------------------------------------------------------------
// buildGt: m = blockIdx.y, 4 v per thread, coalesced via transposed inputs.
// ---------------------------------------------------------------------------
__global__ void k_buildGt() {
    const int m  = blockIdx.y;
    const int v0 = (blockIdx.x * 256 + threadIdx.x) * 4;
    if (v0 >= VP) return;
    float4 f = make_float4(0.f, 0.f, 0.f, 0.f);
    if (m < 456) {
        int k = m / 24, j = m - 24 * (m / 24);       // uniform per row
        float4 a = *(const float4*)(g_jrT + (size_t)k * VP + v0);
        float4 b = *(const float4*)(g_wT  + (size_t)j * VP + v0);
        f = make_float4(a.x * b.x, a.y * b.y, a.z * b.z, a.w * b.w);
    } else if (m < 480) {
        f = *(const float4*)(g_JregT + (size_t)(m - 456) * VP + v0);
    }
    size_t off = (size_t)m * VP + v0;
    *(__half2*)(g_Gh16 + off)     = __floats2half2_rn(f.x, f.y);
    *(__half2*)(g_Gh16 + off + 2) = __floats2half2_rn(f.z, f.w);
}

// ---------------------------------------------------------------------------
// GEMM1: C[m][n] = sum_v Gh[m,v]*Eh[n,v], single-term fp16.
// CTA 128x128, BK=32, 8 warps (4m x 2n -> 32x64 per warp),
// double-buffered dynamic smem (40KB), 1 sync/iter, reg prefetch.
// ---------------------------------------------------------------------------
constexpr int G1_PLANE = 128 * 40;                 // halves per plane
constexpr int G1_BUF   = 2 * G1_PLANE;             // halves per buffer (A+B)
constexpr int G1_SMEM  = 2 * G1_BUF * 2;           // bytes = 40960

__global__ void __launch_bounds__(256, 2) k_gemm1_wmma() {
    using namespace nvcuda;
    extern __shared__ __align__(16) __half dynsmem[];

    const int n0    = blockIdx.x * 128;
    const int m0    = blockIdx.y * 128;
    const int split = blockIdx.z;
    const int tid   = threadIdx.x;
    const int wid   = tid >> 5;
    const int wm    = (wid & 3) * 32;
    const int wn    = (wid >> 2) * 64;

    wmma::fragment<wmma::accumulator, 16, 16, 16, float> acc[2][4];
#pragma unroll
    for (int i = 0; i < 2; ++i)
#pragma unroll
        for (int j = 0; j < 4; ++j)
            wmma::fill_fragment(acc[i][j], 0.f);

    const int kbase = split * KSEG;
    const int nIter = KSEG / 32;                   // 18

    const int r = tid >> 2;                        // 0..63
    const int c = (tid & 3) * 8;                   // 0,8,16,24

    uint4 pA[2], pB[2];

    auto ldg_tile = [&](int kk) {
#pragma unroll
        for (int i = 0; i < 2; ++i) {
            int row = r + 64 * i;
            pA[i] = *(const uint4*)(g_Gh16 + (size_t)(m0 + row) * VP + kk + c);
            pB[i] = *(const uint4*)(g_Eh16 + (size_t)(n0 + row) * VP + kk + c);
        }
    };
    auto sts_tile = [&](int buf) {
        __half* base = dynsmem + buf * G1_BUF;
#pragma unroll
        for (int i = 0; i < 2; ++i) {
            int row = r + 64 * i;
            *(uint4*)(base + row * 40 + c)            = pA[i];
            *(uint4*)(base + G1_PLANE + row * 40 + c) = pB[i];
        }
    };

    ldg_tile(kbase);
    sts_tile(0);
    ldg_tile(kbase + 32);
    __syncthreads();

    for (int it = 0; it < nIter; ++it) {
        const int cur = it & 1;
        if (it + 1 < nIter) sts_tile(1 - cur);
        if (it + 2 < nIter) ldg_tile(kbase + (it + 2) * 32);

        const __half* Ah = dynsmem + cur * G1_BUF;
        const __half* Bh = Ah + G1_PLANE;
#pragma unroll
        for (int k0 = 0; k0 < 32; k0 += 16) {
            wmma::fragment<wmma::matrix_a, 16, 16, 16, __half,
                           wmma::row_major> ah[2];
            wmma::fragment<wmma::matrix_b, 16, 16, 16, __half,
                           wmma::col_major> bh[4];
#pragma unroll
            for (int i = 0; i < 2; ++i)
                wmma::load_matrix_sync(ah[i], Ah + (wm + i * 16) * 40 + k0, 40);
#pragma unroll
            for (int j = 0; j < 4; ++j)
                wmma::load_matrix_sync(bh[j], Bh + (wn + j * 16) * 40 + k0, 40);
#pragma unroll
            for (int i = 0; i < 2; ++i)
#pragma unroll
                for (int j = 0; j < 4; ++j)
                    wmma::mma_sync(acc[i][j], ah[i], bh[j], acc[i][j]);
        }
        __syncthreads();
    }

    float* Co = g_Cp + (size_t)split * (M1 * N1);
#pragma unroll
    for (int i = 0; i < 2; ++i)
#pragma unroll
        for (int j = 0; j < 4; ++j)
            wmma::store_matrix_sync(
                &Co[(size_t)(m0 + wm + i * 16) * N1 + n0 + wn + j * 16],
                acc[i][j], N1, wmma::mem_row_major);
}

// ---------------------------------------------------------------------------
// GEMM2 on WMMA bf16x3 (proven): P = A2 @ CT.
// ---------------------------------------------------------------------------
__global__ void __launch_bounds__(256, 2) k_gemm2_wmma() {
    using namespace nvcuda;

    __shared__ __align__(16) __nv_bfloat16 Ah[32][136];
    __shared__ __align__(16) __nv_bfloat16 Al[32][136];
    __shared__ __align__(16) __nv_bfloat16 Bh[32][136];
    __shared__ __align__(16) __nv_bfloat16 Bl[32][136];

    const int n0    = blockIdx.x * 128;
    const int m0    = blockIdx.y * 128;
    const int split = blockIdx.z;
    const int tid   = threadIdx.x;
    const int wid   = tid >> 5;
    const int wm    = (wid & 1) * 64;
    const int wn    = (wid >> 1) * 32;

    wmma::fragment<wmma::accumulator, 16, 16, 16, float> acc[4][2];
#pragma unroll
    for (int i = 0; i < 4; ++i)
#pragma unroll
        for (int j = 0; j < 2; ++j)
            wmma::fill_fragment(acc[i][j], 0.f);

    const int kbase = split * (KQ / SPLITK2);
    const int nIter = (KQ / SPLITK2) / 32;   // 4

    uint4 pAh[2], pAl[2], pBh[2], pBl[2];
#pragma unroll
    for (int i = 0; i < 2; ++i) {
        int linear = tid + 256 * i;
        int rr = linear >> 4, cc = (linear & 15) * 8;
        pAh[i] = *(const uint4*)(g_A2h + (size_t)(kbase + rr) * B + m0 + cc);
        pAl[i] = *(const uint4*)(g_A2l + (size_t)(kbase + rr) * B + m0 + cc);
        pBh[i] = *(const uint4*)(g_CTh + (size_t)(kbase + rr) * N2 + n0 + cc);
        pBl[i] = *(const uint4*)(g_CTl + (size_t)(kbase + rr) * N2 + n0 + cc);
    }

    for (int it = 0; it < nIter; ++it) {
        __syncthreads();
#pragma unroll
        for (int i = 0; i < 2; ++i) {
            int linear = tid + 256 * i;
            int rr = linear >> 4, cc = (linear & 15) * 8;
            *(uint4*)&Ah[rr][cc] = pAh[i];
            *(uint4*)&Al[rr][cc] = pAl[i];
            *(uint4*)&Bh[rr][cc] = pBh[i];
            *(uint4*)&Bl[rr][cc] = pBl[i];
        }
        __syncthreads();
        if (it + 1 < nIter) {
            int kk = kbase + (it + 1) * 32;
#pragma unroll
            for (int i = 0; i < 2; ++i) {
                int linear = tid + 256 * i;
                int rr = linear >> 4, cc = (linear & 15) * 8;
                pAh[i] = *(const uint4*)(g_A2h + (size_t)(kk + rr) * B + m0 + cc);
                pAl[i] = *(const uint4*)(g_A2l + (size_t)(kk + rr) * B + m0 + cc);
                pBh[i] = *(const uint4*)(g_CTh + (size_t)(kk + rr) * N2 + n0 + cc);
                pBl[i] = *(const uint4*)(g_CTl + (size_t)(kk + rr) * N2 + n0 + cc);
            }
        }
#pragma unroll
        for (int k0 = 0; k0 < 32; k0 += 16) {
            wmma::fragment<wmma::matrix_a, 16, 16, 16, __nv_bfloat16,
                           wmma::col_major> ah[4], al[4];
            wmma::fragment<wmma::matrix_b, 16, 16, 16, __nv_bfloat16,
                           wmma::row_major> bh[2], bl[2];
#pragma unroll
            for (int i = 0; i < 4; ++i) {
                wmma::load_matrix_sync(ah[i], &Ah[k0][wm + i * 16], 136);
                wmma::load_matrix_sync(al[i], &Al[k0][wm + i * 16], 136);
            }
#pragma unroll
            for (int j = 0; j < 2; ++j) {
                wmma::load_matrix_sync(bh[j], &Bh[k0][wn + j * 16], 136);
                wmma::load_matrix_sync(bl[j], &Bl[k0][wn + j * 16], 136);
            }
#pragma unroll
            for (int i = 0; i < 4; ++i)
#pragma unroll
                for (int j = 0; j < 2; ++j) {
                    wmma::mma_sync(acc[i][j], ah[i], bh[j], acc[i][j]);
                    wmma::mma_sync(acc[i][j], al[i], bh[j], acc[i][j]);
                    wmma::mma_sync(acc[i][j], ah[i], bl[j], acc[i][j]);
                }
        }
    }

    float* Po = g_P + (size_t)split * PSTR;
#pragma unroll
    for (int i = 0; i < 4; ++i)
#pragma unroll
        for (int j = 0; j < 2; ++j)
            wmma::store_matrix_sync(
                &Po[(size_t)(m0 + wm + i * 16) * N2 + n0 + wn + j * 16],
                acc[i][j], N2, wmma::mem_row_major);
}

// ---------------------------------------------------------------------------
// Reduce GEMM1 split-K partials into CTh/CTl (bf16), S, JT.
// ---------------------------------------------------------------------------
__global__ void k_reduce() {
    int idx = blockIdx.x * blockDim.x + threadIdx.x;
    const int NCT = KQ * N2;
    if (idx < NCT) {
        int q = idx / N2, m = idx - q * N2;
        float val = 0.f;
        if (m < 1368 && q < 218) {
            int kj = m / 3, c = m - 3 * kj;
            int col;
            if (q == 0)        col = 651 + c;
            else if (q <= 10)  col = 621 + (q - 1) * 3 + c;
            else               col = (q - 11) * 3 + c;
            size_t off = (size_t)kj * N1 + col;
#pragma unroll
            for (int s = 0; s < SPLITK1; ++s)
                val += g_Cp[(size_t)s * (M1 * N1) + off];
        }
        __nv_bfloat16 hi, lo;
        split_bf16(val, hi, lo);
        g_CTh[idx] = hi;
        g_CTl[idx] = lo;
    } else if (idx < NCT + 456) {
        int kj = idx - NCT;
        float val = 0.f;
#pragma unroll
        for (int s = 0; s < SPLITK1; ++s)
            val += g_Cp[(size_t)s * (M1 * N1) + (size_t)kj * N1 + 654];
        g_S[kj] = val;
    } else if (idx < NCT + 456 + 24 * 33) {
        int t2 = idx - NCT - 456;
        int j = t2 / 33, t = t2 - 33 * j;
        float val = 0.f;
#pragma unroll
        for (int s = 0; s < SPLITK1; ++s)
            val += g_Cp[(size_t)s * (M1 * N1) + (size_t)(456 + j) * N1 + 621 + t];
        g_JT[t2] = val;
    }
}

// ---------------------------------------------------------------------------
// Per-body prep (one warp / body). Emits A2 column as bf16 hi/lo.
// ---------------------------------------------------------------------------
__global__ void k_prep(const float* __restrict__ beta,
                       const float* __restrict__ theta) {
    const int b = blockIdx.x;
    const int lane = threadIdx.x;

    __shared__ float Rsm[24][9];
    __shared__ float Jm[24][3];
    __shared__ float Ag[24][12];
    __shared__ float bet[10];

    if (lane < 10) bet[lane] = beta[b * NB + lane];
    __syncwarp();

    if (lane < 24) {
        float tx = theta[b * 72 + lane * 3 + 0];
        float ty = theta[b * 72 + lane * 3 + 1];
        float tz = theta[b * 72 + lane * 3 + 2];
        float ax = tx + 1e-8f, ay = ty + 1e-8f, az = tz + 1e-8f;
        float angle = sqrtf(ax * ax + ay * ay + az * az);
        float half = 0.5f * angle;
        float s = sinf(half), cw = cosf(half);
        float vx = tx / angle * s, vy = ty / angle * s, vz = tz / angle * s;
        float qn = sqrtf(cw * cw + vx * vx + vy * vy + vz * vz);
        float w = cw / qn, x = vx / qn, y = vy / qn, z = vz / qn;
        Rsm[lane][0] = 1.f - 2.f * (y * y + z * z);
        Rsm[lane][1] = 2.f * (x * y - w * z);
        Rsm[lane][2] = 2.f * (x * z + w * y);
        Rsm[lane][3] = 2.f * (x * y + w * z);
        Rsm[lane][4] = 1.f - 2.f * (x * x + z * z);
        Rsm[lane][5] = 2.f * (y * z - w * x);
        Rsm[lane][6] = 2.f * (x * z - w * y);
        Rsm[lane][7] = 2.f * (y * z + w * x);
        Rsm[lane][8] = 1.f - 2.f * (x * x + y * y);
#pragma unroll
        for (int c = 0; c < 3; ++c) {
            float val = g_JT[lane * 33 + 30 + c];
#pragma unroll
            for (int n = 0; n < 10; ++n)
                val += bet[n] * g_JT[lane * 33 + n * 3 + c];
            Jm[lane][c] = val;
        }
    }
    __syncwarp();

    for (int q = lane; q < KQ; q += 32) {
        float val;
        if (q == 0) val = 1.f;
        else if (q <= 10) val = bet[q - 1];
        else if (q < 218) {
            int p = q - 11;
            int i = p / 9 + 1, e = p - 9 * (p / 9);
            val = Rsm[i][e] - ((e == 0 || e == 4 || e == 8) ? 1.f : 0.f);
        } else val = 0.f;
        __nv_bfloat16 hi, lo;
        split_bf16(val, hi, lo);
        g_A2h[q * B + b] = hi;
        g_A2l[q * B + b] = lo;
    }

    const int r = lane >> 2, cc = lane & 3;
    for (int i = 0; i < 24; ++i) {
        if (lane < 12) {
            float val;
            if (i == 0) {
                val = (cc < 3) ? Rsm[0][r * 3 + cc] * (cc == 0 ? 1.f : -1.f)
                               : Jm[0][r];
            } else {
                int par = c_par[i];
                float l0, l1, l2;
                if (cc < 3) {
                    l0 = Rsm[i][0 * 3 + cc];
                    l1 = Rsm[i][1 * 3 + cc];
                    l2 = Rsm[i][2 * 3 + cc];
                } else {
                    l0 = Jm[i][0] - Jm[par][0];
                    l1 = Jm[i][1] - Jm[par][1];
                    l2 = Jm[i][2] - Jm[par][2];
                }
                val = Ag[par][r * 4 + 0] * l0 + Ag[par][r * 4 + 1] * l1 +
                      Ag[par][r * 4 + 2] * l2;
                if (cc == 3) val += Ag[par][r * 4 + 3];
            }
            Ag[i][r * 4 + cc] = val;
        }
        __syncwarp();
    }

    for (int idx = lane; idx < 288; idx += 32) {
        int j = idx / 12, e = idx - 12 * j;
        float out;
        if (e < 9) {
            int rr = e / 3, c = e - 3 * rr;
            out = Ag[j][rr * 4 + c];
        } else {
            int rr = e - 9;
            out = Ag[j][rr * 4 + 3] -
                  (Ag[j][rr * 4 + 0] * Jm[j][0] + Ag[j][rr * 4 + 1] * Jm[j][1] +
                   Ag[j][rr * 4 + 2] * Jm[j][2]);
        }
        g_Rg[b * 288 + idx] = out;
    }
}

// ---------------------------------------------------------------------------
// joints epilogue (folds 2 GEMM2 split-K partials)
// ---------------------------------------------------------------------------
__global__ void k_joints(const float* __restrict__ trans,
                         float* __restrict__ out) {
    const int b = blockIdx.x;
    const int tid = threadIdx.x;
    __shared__ float sA[288];
    __shared__ float sS[456];
    for (int i = tid; i < 288; i += 64) sA[i] = g_Rg[b * 288 + i];
    for (int i = tid; i < 456; i += 64) sS[i] = g_S[i];
    __syncthreads();
    if (tid < 57) {
        int k = tid / 3, r = tid - 3 * k;
        float acc = trans[b * 3 + r];
        const float* Pb0 = &g_P[(size_t)b * N2];
        const float* Pb1 = &g_P[(size_t)PSTR + (size_t)b * N2];
#pragma unroll
        for (int j = 0; j < 24; ++j) {
            const float* M = &sA[j * 12];
            int m = (k * 24 + j) * 3;
            float p0 = Pb0[m + 0] + Pb1[m + 0];
            float p1 = Pb0[m + 1] + Pb1[m + 1];
            float p2 = Pb0[m + 2] + Pb1[m + 2];
            acc += M[r * 3 + 0] * p0 + M[r * 3 + 1] * p1 + M[r * 3 + 2] * p2 +
                   M[9 + r] * sS[k * 24 + j];
        }
        out[b * 57 + tid] = acc;
    }
}

} // namespace smpl

extern "C" void kernel_launch(void* const* d_in, const int* in_sizes, int n_in,
                              void* d_out, int out_size) {
    using namespace smpl;
    const float* beta       = (const float*)d_in[0];
    const float* theta      = (const float*)d_in[1];
    const float* trans      = (const float*)d_in[2];
    const float* v_template = (const float*)d_in[3];
    const float* shapedirs  = (const float*)d_in[4];
    const float* J_reg      = (const float*)d_in[5];
    const float* posedirs   = (const float*)d_in[6];
    const float* joint_reg  = (const float*)d_in[7];
    const float* weights    = (const float*)d_in[8];
    float* out = (float*)d_out;

    cudaFuncSetAttribute(k_gemm1_wmma,
                         cudaFuncAttributeMaxDynamicSharedMemorySize, G1_SMEM);

    // 0) Transpose regressors -> [c][v] (one launch)
    {
        dim3 grid(VP / 256, NK + NJ + NJ);        // 27 x 67
        k_transpose_all<<<grid, 256>>>(joint_reg, weights, J_reg);
    }

    // 1) Build fp16 operands
    {
        dim3 grid(VP / 256, 207);
        k_buildEh_pose<<<grid, 128>>>(posedirs);
    }
    {
        dim3 grid(VP / 256, 147);
        k_buildEh_rest<<<grid, 128>>>(shapedirs, v_template);
    }
    {
        dim3 grid((VP / 4 + 255) / 256, M1);      // 7 x 512
        k_buildGt<<<grid, 256>>>();
    }

    // 2) GEMM1 single-term fp16, split-K = 12
    {
        dim3 grid(N1 / 128, M1 / 128, SPLITK1);   // 6 x 4 x 12 = 288 CTAs
        k_gemm1_wmma<<<grid, 256, G1_SMEM>>>();
    }

    // 3) Reduce partials -> CTh/CTl / S / JT
    {
        int n = KQ * N2 + 456 + 24 * 33;
        k_reduce<<<(n + 255) / 256, 256>>>();
    }

    // 4) Per-body prep
    k_prep<<<B, 32>>>(beta, theta);

    // 5) GEMM2 on WMMA bf16x3, split-K = 2
    {
        dim3 grid(N2 / 128, B / 128, SPLITK2);    // 11 x 8 x 2
        k_gemm2_wmma<<<grid, 256>>>();
    }

    // 6) Joints epilogue
    k_joints<<<B, 64>>>(trans, out);
}

// round 8
// speedup vs baseline: 2.2218x; 1.2301x over previous
#include <cuda_runtime.h>
#include <cuda_fp16.h>
#include <mma.h>
#include <cstdint>

// ---------------------------------------------------------------------------
// SMPL fused pipeline, round 8:
//  - GEMM1 fp16 single-term, 256x128 CTA tile, 64x64 warp tile
//  - fused buildG (smem-cached regressor slices)
//  - per-row reduce with K-contiguous CTt output
//  - GEMM2 fp16 2-term (A2 hi/lo x CT), K-contiguous operands
// ---------------------------------------------------------------------------

namespace smpl {

constexpr int V    = 6890;
constexpr int NB   = 10;
constexpr int NJ   = 24;
constexpr int NK   = 19;
constexpr int B    = 1024;

constexpr int VP   = 6912;
constexpr int M1   = 512;
constexpr int N1   = 768;
constexpr int SPLITK1 = 12;           // KSEG = 576 = 18*32
constexpr int KSEG = VP / SPLITK1;
constexpr int KQ   = 256;             // 218 padded
constexpr int N2   = 1408;            // 1368 padded
constexpr int SPLITK2 = 2;
constexpr int PSTR = B * N2;

// GEMM1 fp16 operands (K = v contiguous)
__device__ __align__(256) __half g_Gh16[M1 * VP];
__device__ __align__(256) __half g_Eh16[N1 * VP];

// GEMM2 operands, all K(=q) contiguous
__device__ __align__(256) __half g_A2h[B * KQ];
__device__ __align__(256) __half g_A2l[B * KQ];
__device__ __align__(256) __half g_CTt[N2 * KQ];    // CTt[m][q] = CT[q][m]

__device__ __align__(256) float g_Cp [SPLITK1 * M1 * N1];
__device__ __align__(256) float g_S  [456];
__device__ __align__(256) float g_JT [24 * 33];
__device__ __align__(256) float g_Rg [B * 288];
__device__ __align__(256) float g_P  [SPLITK2 * B * N2];

__constant__ int c_par[24] = {-1,0,0,0,1,2,3,4,5,6,7,8,9,9,9,12,13,14,16,17,18,19,20,21};

__device__ __forceinline__ void split_h16(float v, __half& hi, __half& lo) {
    hi = __float2half_rn(v);
    lo = __float2half_rn(v - __half2float(hi));
}

// ---------------------------------------------------------------------------
// Fused buildG: one CTA per 128-v slice; regressor columns cached in smem,
// emits all 512 G rows (456 jr*w, 24 Jreg, 32 zero pad).
// ---------------------------------------------------------------------------
__global__ void __launch_bounds__(128) k_buildG(
        const float* __restrict__ joint_reg,   // [V][19]
        const float* __restrict__ weights,     // [V][24]
        const float* __restrict__ J_reg) {     // [V][24]
    __shared__ float s_jr[NK][128];
    __shared__ float s_w [NJ][128];
    __shared__ float s_J [NJ][128];

    const int tid = threadIdx.x;
    const int v   = blockIdx.x * 128 + tid;
    if (v < V) {
#pragma unroll
        for (int c = 0; c < NK; ++c) s_jr[c][tid] = joint_reg[(size_t)v * NK + c];
#pragma unroll
        for (int c = 0; c < NJ; ++c) s_w[c][tid]  = weights[(size_t)v * NJ + c];
#pragma unroll
        for (int c = 0; c < NJ; ++c) s_J[c][tid]  = J_reg[(size_t)v * NJ + c];
    } else {
#pragma unroll
        for (int c = 0; c < NK; ++c) s_jr[c][tid] = 0.f;
#pragma unroll
        for (int c = 0; c < NJ; ++c) s_w[c][tid]  = 0.f;
#pragma unroll
        for (int c = 0; c < NJ; ++c) s_J[c][tid]  = 0.f;
    }
    __syncthreads();

    __half* dst = g_Gh16 + (blockIdx.x * 128 + tid);
    for (int k = 0; k < NK; ++k) {
        float a = s_jr[k][tid];
#pragma unroll
        for (int j = 0; j < NJ; ++j)
            dst[(size_t)(k * NJ + j) * VP] = __float2half_rn(a * s_w[j][tid]);
    }
#pragma unroll
    for (int j = 0; j < NJ; ++j)
        dst[(size_t)(456 + j) * VP] = __float2half_rn(s_J[j][tid]);
#pragma unroll
    for (int m = 480; m < M1; ++m)
        dst[(size_t)m * VP] = __float2half_rn(0.f);
}

// ---------------------------------------------------------------------------
// buildEh pose rows: p = blockIdx.y, 4 v per thread.
// ---------------------------------------------------------------------------
__global__ void k_buildEh_pose(const float* __restrict__ posedirs) {
    const int p  = blockIdx.y;
    const int vv = (blockIdx.x * 192 + threadIdx.x) * 4;
    const float* src = posedirs + (size_t)p * (V * 3);
    float f[4][3];
#pragma unroll
    for (int u = 0; u < 4; ++u) {
        int v = vv + u;
#pragma unroll
        for (int c = 0; c < 3; ++c)
            f[u][c] = (v < V) ? src[3 * v + c] : 0.f;
    }
#pragma unroll
    for (int c = 0; c < 3; ++c) {
        __half2 h0 = __floats2half2_rn(f[0][c], f[1][c]);
        __half2 h1 = __floats2half2_rn(f[2][c], f[3][c]);
        __half* dst = g_Eh16 + (size_t)(3 * p + c) * VP + vv;
        *(__half2*)dst       = h0;
        *(__half2*)(dst + 2) = h1;
    }
}

// ---------------------------------------------------------------------------
// buildEh rest rows: n = 621 + blockIdx.y (147 rows incl pad)
// ---------------------------------------------------------------------------
__global__ void k_buildEh_rest(const float* __restrict__ shapedirs,
                               const float* __restrict__ v_template) {
    const int n  = 621 + blockIdx.y;
    const int vv = (blockIdx.x * 192 + threadIdx.x) * 4;
    float f[4] = {0.f, 0.f, 0.f, 0.f};
    if (n < 651) {
        int t = n - 621, q = t / 3, c = t - 3 * q;   // uniform
        const float* src = shapedirs + (size_t)q * (V * 3);
#pragma unroll
        for (int u = 0; u < 4; ++u)
            if (vv + u < V) f[u] = src[3 * (vv + u) + c];
    } else if (n < 654) {
        int c = n - 651;
#pragma unroll
        for (int u = 0; u < 4; ++u)
            if (vv + u < V) f[u] = v_template[3 * (vv + u) + c];
    } else if (n == 654) {
#pragma unroll
        for (int u = 0; u < 4; ++u)
            if (vv + u < V) f[u] = 1.f;
    }
    __half* dst = g_Eh16 + (size_t)n * VP + vv;
    *(__half2*)dst       = __floats2half2_rn(f[0], f[1]);
    *(__half2*)(dst + 2) = __floats2half2_rn(f[2], f[3]);
}

// ---------------------------------------------------------------------------
// GEMM1: C[m][n] = sum_v Gh[m,v]*Eh[n,v], fp16 single term.
// CTA 256x128, BK=32, 8 warps as 4m x 2n (64x64 per warp),
// double-buffered dynamic smem (60KB), 1 sync/iter.
// ---------------------------------------------------------------------------
constexpr int G1A    = 256 * 40;               // A plane halves
constexpr int G1B    = 128 * 40;               // B plane halves
constexpr int G1_BUF = G1A + G1B;
constexpr int G1_SMEM = 2 * G1_BUF * 2;        // 61440 bytes

__global__ void __launch_bounds__(256, 1) k_gemm1_wmma() {
    using namespace nvcuda;
    extern __shared__ __align__(16) __half dynsmem[];

    const int n0    = blockIdx.x * 128;
    const int m0    = blockIdx.y * 256;
    const int split = blockIdx.z;
    const int tid   = threadIdx.x;
    const int wid   = tid >> 5;
    const int wm    = (wid & 3) * 64;
    const int wn    = (wid >> 2) * 64;

    wmma::fragment<wmma::accumulator, 16, 16, 16, float> acc[4][4];
#pragma unroll
    for (int i = 0; i < 4; ++i)
#pragma unroll
        for (int j = 0; j < 4; ++j)
            wmma::fill_fragment(acc[i][j], 0.f);

    const int kbase = split * KSEG;
    const int nIter = KSEG / 32;               // 18

    uint4 pA[4], pB[2];

    auto ldg_tile = [&](int kk) {
#pragma unroll
        for (int i = 0; i < 4; ++i) {
            int linear = tid + 256 * i;
            int row = linear >> 2, c = (linear & 3) * 8;
            pA[i] = *(const uint4*)(g_Gh16 + (size_t)(m0 + row) * VP + kk + c);
        }
#pragma unroll
        for (int i = 0; i < 2; ++i) {
            int linear = tid + 256 * i;
            int row = linear >> 2, c = (linear & 3) * 8;
            pB[i] = *(const uint4*)(g_Eh16 + (size_t)(n0 + row) * VP + kk + c);
        }
    };
    auto sts_tile = [&](int buf) {
        __half* base = dynsmem + buf * G1_BUF;
#pragma unroll
        for (int i = 0; i < 4; ++i) {
            int linear = tid + 256 * i;
            int row = linear >> 2, c = (linear & 3) * 8;
            *(uint4*)(base + row * 40 + c) = pA[i];
        }
#pragma unroll
        for (int i = 0; i < 2; ++i) {
            int linear = tid + 256 * i;
            int row = linear >> 2, c = (linear & 3) * 8;
            *(uint4*)(base + G1A + row * 40 + c) = pB[i];
        }
    };

    ldg_tile(kbase);
    sts_tile(0);
    ldg_tile(kbase + 32);
    __syncthreads();

    for (int it = 0; it < nIter; ++it) {
        const int cur = it & 1;
        if (it + 1 < nIter) sts_tile(1 - cur);
        if (it + 2 < nIter) ldg_tile(kbase + (it + 2) * 32);

        const __half* Ah = dynsmem + cur * G1_BUF;
        const __half* Bh = Ah + G1A;
#pragma unroll
        for (int k0 = 0; k0 < 32; k0 += 16) {
            wmma::fragment<wmma::matrix_a, 16, 16, 16, __half,
                           wmma::row_major> ah[4];
            wmma::fragment<wmma::matrix_b, 16, 16, 16, __half,
                           wmma::col_major> bh[4];
#pragma unroll
            for (int i = 0; i < 4; ++i)
                wmma::load_matrix_sync(ah[i], Ah + (wm + i * 16) * 40 + k0, 40);
#pragma unroll
            for (int j = 0; j < 4; ++j)
                wmma::load_matrix_sync(bh[j], Bh + (wn + j * 16) * 40 + k0, 40);
#pragma unroll
            for (int i = 0; i < 4; ++i)
#pragma unroll
                for (int j = 0; j < 4; ++j)
                    wmma::mma_sync(acc[i][j], ah[i], bh[j], acc[i][j]);
        }
        __syncthreads();
    }

    float* Co = g_Cp + (size_t)split * (M1 * N1);
#pragma unroll
    for (int i = 0; i < 4; ++i)
#pragma unroll
        for (int j = 0; j < 4; ++j)
            wmma::store_matrix_sync(
                &Co[(size_t)(m0 + wm + i * 16) * N1 + n0 + wn + j * 16],
                acc[i][j], N1, wmma::mem_row_major);
}

// ---------------------------------------------------------------------------
// Reduce: per-kj-row blocks; coalesced plane sums staged in smem;
// emits CTt[m][q] (fp16, K-contiguous), S, JT; pads CTt rows/cols with 0.
// grid = 520 x 128 threads.
// ---------------------------------------------------------------------------
__global__ void __launch_bounds__(128) k_reduce() {
    const int blk = blockIdx.x;
    const int tid = threadIdx.x;

    if (blk < 456) {
        __shared__ float s[656];
        for (int col = tid; col < 655; col += 128) {
            float val = 0.f;
            size_t off = (size_t)blk * N1 + col;
#pragma unroll
            for (int sp = 0; sp < SPLITK1; ++sp)
                val += g_Cp[(size_t)sp * (M1 * N1) + off];
            s[col] = val;
        }
        __syncthreads();
#pragma unroll
        for (int c = 0; c < 3; ++c) {
            int m = 3 * blk + c;
            for (int q = tid; q < KQ; q += 128) {
                float val = 0.f;
                if (q == 0)        val = s[651 + c];
                else if (q <= 10)  val = s[621 + (q - 1) * 3 + c];
                else if (q < 218)  val = s[(q - 11) * 3 + c];
                g_CTt[(size_t)m * KQ + q] = __float2half_rn(val);
            }
        }
        if (tid == 0) g_S[blk] = s[654];
    } else if (blk < 480) {
        int j = blk - 456;
        if (tid < 33) {
            float val = 0.f;
            size_t off = (size_t)(456 + j) * N1 + 621 + tid;
#pragma unroll
            for (int sp = 0; sp < SPLITK1; ++sp)
                val += g_Cp[(size_t)sp * (M1 * N1) + off];
            g_JT[j * 33 + tid] = val;
        }
    } else {
        int m = 1368 + (blk - 480);               // pad rows 1368..1407
        for (int q = tid; q < KQ; q += 128)
            g_CTt[(size_t)m * KQ + q] = __float2half_rn(0.f);
    }
}

// ---------------------------------------------------------------------------
// Per-body prep (one warp / body). Emits A2 row [b][q] as fp16 hi/lo.
// ---------------------------------------------------------------------------
__global__ void k_prep(const float* __restrict__ beta,
                       const float* __restrict__ theta) {
    const int b = blockIdx.x;
    const int lane = threadIdx.x;

    __shared__ float Rsm[24][9];
    __shared__ float Jm[24][3];
    __shared__ float Ag[24][12];
    __shared__ float bet[10];

    if (lane < 10) bet[lane] = beta[b * NB + lane];
    __syncwarp();

    if (lane < 24) {
        float tx = theta[b * 72 + lane * 3 + 0];
        float ty = theta[b * 72 + lane * 3 + 1];
        float tz = theta[b * 72 + lane * 3 + 2];
        float ax = tx + 1e-8f, ay = ty + 1e-8f, az = tz + 1e-8f;
        float angle = sqrtf(ax * ax + ay * ay + az * az);
        float half = 0.5f * angle;
        float s = sinf(half), cw = cosf(half);
        float vx = tx / angle * s, vy = ty / angle * s, vz = tz / angle * s;
        float qn = sqrtf(cw * cw + vx * vx + vy * vy + vz * vz);
        float w = cw / qn, x = vx / qn, y = vy / qn, z = vz / qn;
        Rsm[lane][0] = 1.f - 2.f * (y * y + z * z);
        Rsm[lane][1] = 2.f * (x * y - w * z);
        Rsm[lane][2] = 2.f * (x * z + w * y);
        Rsm[lane][3] = 2.f * (x * y + w * z);
        Rsm[lane][4] = 1.f - 2.f * (x * x + z * z);
        Rsm[lane][5] = 2.f * (y * z - w * x);
        Rsm[lane][6] = 2.f * (x * z - w * y);
        Rsm[lane][7] = 2.f * (y * z + w * x);
        Rsm[lane][8] = 1.f - 2.f * (x * x + y * y);
#pragma unroll
        for (int c = 0; c < 3; ++c) {
            float val = g_JT[lane * 33 + 30 + c];
#pragma unroll
            for (int n = 0; n < 10; ++n)
                val += bet[n] * g_JT[lane * 33 + n * 3 + c];
            Jm[lane][c] = val;
        }
    }
    __syncwarp();

    for (int q = lane; q < KQ; q += 32) {
        float val;
        if (q == 0) val = 1.f;
        else if (q <= 10) val = bet[q - 1];
        else if (q < 218) {
            int p = q - 11;
            int i = p / 9 + 1, e = p - 9 * (p / 9);
            val = Rsm[i][e] - ((e == 0 || e == 4 || e == 8) ? 1.f : 0.f);
        } else val = 0.f;
        __half hi, lo;
        split_h16(val, hi, lo);
        g_A2h[(size_t)b * KQ + q] = hi;
        g_A2l[(size_t)b * KQ + q] = lo;
    }

    const int r = lane >> 2, cc = lane & 3;
    for (int i = 0; i < 24; ++i) {
        if (lane < 12) {
            float val;
            if (i == 0) {
                val = (cc < 3) ? Rsm[0][r * 3 + cc] * (cc == 0 ? 1.f : -1.f)
                               : Jm[0][r];
            } else {
                int par = c_par[i];
                float l0, l1, l2;
                if (cc < 3) {
                    l0 = Rsm[i][0 * 3 + cc];
                    l1 = Rsm[i][1 * 3 + cc];
                    l2 = Rsm[i][2 * 3 + cc];
                } else {
                    l0 = Jm[i][0] - Jm[par][0];
                    l1 = Jm[i][1] - Jm[par][1];
                    l2 = Jm[i][2] - Jm[par][2];
                }
                val = Ag[par][r * 4 + 0] * l0 + Ag[par][r * 4 + 1] * l1 +
                      Ag[par][r * 4 + 2] * l2;
                if (cc == 3) val += Ag[par][r * 4 + 3];
            }
            Ag[i][r * 4 + cc] = val;
        }
        __syncwarp();
    }

    for (int idx = lane; idx < 288; idx += 32) {
        int j = idx / 12, e = idx - 12 * j;
        float out;
        if (e < 9) {
            int rr = e / 3, c = e - 3 * rr;
            out = Ag[j][rr * 4 + c];
        } else {
            int rr = e - 9;
            out = Ag[j][rr * 4 + 3] -
                  (Ag[j][rr * 4 + 0] * Jm[j][0] + Ag[j][rr * 4 + 1] * Jm[j][1] +
                   Ag[j][rr * 4 + 2] * Jm[j][2]);
        }
        g_Rg[b * 288 + idx] = out;
    }
}

// ---------------------------------------------------------------------------
// GEMM2: P[b][m] = sum_q A2[b,q]*CTt[m,q], fp16 2-term (A2 hi/lo x CT).
// CTA 128x128, BK=32, 8 warps as 4b x 2m (32x64 per warp), split-K=2.
// Single-buffered static smem with register prefetch.
// ---------------------------------------------------------------------------
__global__ void __launch_bounds__(256, 2) k_gemm2_wmma() {
    using namespace nvcuda;

    __shared__ __align__(16) __half Ash[128][40];
    __shared__ __align__(16) __half Asl[128][40];
    __shared__ __align__(16) __half Bs [128][40];

    const int n0    = blockIdx.x * 128;    // m (output col) tile
    const int b0    = blockIdx.y * 128;    // batch tile
    const int split = blockIdx.z;
    const int tid   = threadIdx.x;
    const int wid   = tid >> 5;
    const int wb    = (wid & 3) * 32;
    const int wn    = (wid >> 2) * 64;

    wmma::fragment<wmma::accumulator, 16, 16, 16, float> acc[2][4];
#pragma unroll
    for (int i = 0; i < 2; ++i)
#pragma unroll
        for (int j = 0; j < 4; ++j)
            wmma::fill_fragment(acc[i][j], 0.f);

    const int kbase = split * (KQ / SPLITK2);
    const int nIter = (KQ / SPLITK2) / 32;     // 4

    uint4 pAh[2], pAl[2], pB[2];
    auto ldg_tile = [&](int kk) {
#pragma unroll
        for (int i = 0; i < 2; ++i) {
            int linear = tid + 256 * i;
            int row = linear >> 2, c = (linear & 3) * 8;
            pAh[i] = *(const uint4*)(g_A2h + (size_t)(b0 + row) * KQ + kk + c);
            pAl[i] = *(const uint4*)(g_A2l + (size_t)(b0 + row) * KQ + kk + c);
            pB[i]  = *(const uint4*)(g_CTt + (size_t)(n0 + row) * KQ + kk + c);
        }
    };

    ldg_tile(kbase);

    for (int it = 0; it < nIter; ++it) {
        __syncthreads();
#pragma unroll
        for (int i = 0; i < 2; ++i) {
            int linear = tid + 256 * i;
            int row = linear >> 2, c = (linear & 3) * 8;
            *(uint4*)&Ash[row][c] = pAh[i];
            *(uint4*)&Asl[row][c] = pAl[i];
            *(uint4*)&Bs[row][c]  = pB[i];
        }
        __syncthreads();
        if (it + 1 < nIter) ldg_tile(kbase + (it + 1) * 32);

#pragma unroll
        for (int k0 = 0; k0 < 32; k0 += 16) {
            wmma::fragment<wmma::matrix_a, 16, 16, 16, __half,
                           wmma::row_major> ah[2], al[2];
            wmma::fragment<wmma::matrix_b, 16, 16, 16, __half,
                           wmma::col_major> bh[4];
#pragma unroll
            for (int i = 0; i < 2; ++i) {
                wmma::load_matrix_sync(ah[i], &Ash[wb + i * 16][k0], 40);
                wmma::load_matrix_sync(al[i], &Asl[wb + i * 16][k0], 40);
            }
#pragma unroll
            for (int j = 0; j < 4; ++j)
                wmma::load_matrix_sync(bh[j], &Bs[wn + j * 16][k0], 40);
#pragma unroll
            for (int i = 0; i < 2; ++i)
#pragma unroll
                for (int j = 0; j < 4; ++j) {
                    wmma::mma_sync(acc[i][j], ah[i], bh[j], acc[i][j]);
                    wmma::mma_sync(acc[i][j], al[i], bh[j], acc[i][j]);
                }
        }
    }

    float* Po = g_P + (size_t)split * PSTR;
#pragma unroll
    for (int i = 0; i < 2; ++i)
#pragma unroll
        for (int j = 0; j < 4; ++j)
            wmma::store_matrix_sync(
                &Po[(size_t)(b0 + wb + i * 16) * N2 + n0 + wn + j * 16],
                acc[i][j], N2, wmma::mem_row_major);
}

// ---------------------------------------------------------------------------
// joints epilogue (folds 2 GEMM2 split-K partials)
// ---------------------------------------------------------------------------
__global__ void k_joints(const float* __restrict__ trans,
                         float* __restrict__ out) {
    const int b = blockIdx.x;
    const int tid = threadIdx.x;
    __shared__ float sA[288];
    __shared__ float sS[456];
    for (int i = tid; i < 288; i += 64) sA[i] = g_Rg[b * 288 + i];
    for (int i = tid; i < 456; i += 64) sS[i] = g_S[i];
    __syncthreads();
    if (tid < 57) {
        int k = tid / 3, r = tid - 3 * k;
        float acc = trans[b * 3 + r];
        const float* Pb0 = &g_P[(size_t)b * N2];
        const float* Pb1 = &g_P[(size_t)PSTR + (size_t)b * N2];
#pragma unroll
        for (int j = 0; j < 24; ++j) {
            const float* M = &sA[j * 12];
            int m = (k * 24 + j) * 3;
            float p0 = Pb0[m + 0] + Pb1[m + 0];
            float p1 = Pb0[m + 1] + Pb1[m + 1];
            float p2 = Pb0[m + 2] + Pb1[m + 2];
            acc += M[r * 3 + 0] * p0 + M[r * 3 + 1] * p1 + M[r * 3 + 2] * p2 +
                   M[9 + r] * sS[k * 24 + j];
        }
        out[b * 57 + tid] = acc;
    }
}

} // namespace smpl

extern "C" void kernel_launch(void* const* d_in, const int* in_sizes, int n_in,
                              void* d_out, int out_size) {
    using namespace smpl;
    const float* beta       = (const float*)d_in[0];
    const float* theta      = (const float*)d_in[1];
    const float* trans      = (const float*)d_in[2];
    const float* v_template = (const float*)d_in[3];
    const float* shapedirs  = (const float*)d_in[4];
    const float* J_reg      = (const float*)d_in[5];
    const float* posedirs   = (const float*)d_in[6];
    const float* joint_reg  = (const float*)d_in[7];
    const float* weights    = (const float*)d_in[8];
    float* out = (float*)d_out;

    cudaFuncSetAttribute(k_gemm1_wmma,
                         cudaFuncAttributeMaxDynamicSharedMemorySize, G1_SMEM);

    // 1) Build fp16 operands
    k_buildG<<<VP / 128, 128>>>(joint_reg, weights, J_reg);
    {
        dim3 grid(VP / 768, 207);                 // 9 x 207, 4 v/thread
        k_buildEh_pose<<<grid, 192>>>(posedirs);
    }
    {
        dim3 grid(VP / 768, 147);                 // 9 x 147
        k_buildEh_rest<<<grid, 192>>>(shapedirs, v_template);
    }

    // 2) GEMM1 fp16 single-term, 256x128 tiles, split-K = 12
    {
        dim3 grid(N1 / 128, M1 / 256, SPLITK1);   // 6 x 2 x 12 = 144 CTAs
        k_gemm1_wmma<<<grid, 256, G1_SMEM>>>();
    }

    // 3) Reduce partials -> CTt / S / JT
    k_reduce<<<520, 128>>>();

    // 4) Per-body prep
    k_prep<<<B, 32>>>(beta, theta);

    // 5) GEMM2 fp16 2-term, split-K = 2
    {
        dim3 grid(N2 / 128, B / 128, SPLITK2);    // 11 x 8 x 2
        k_gemm2_wmma<<<grid, 256>>>();
    }

    // 6) Joints epilogue
    k_joints<<<B, 64>>>(trans, out);
}

// round 9
// speedup vs baseline: 2.2730x; 1.0230x over previous
#include <cuda_runtime.h>
#include <cuda_fp16.h>
#include <mma.h>
#include <cstdint>

// ---------------------------------------------------------------------------
// SMPL fused pipeline, round 9:
//  - GEMM1 fp16 single-term, 256x128 CTA tile, 512 threads (16 warps)
//  - GEMM2 fp16 2-term, split-K = 1
//  - merged buildE kernel
// ---------------------------------------------------------------------------

namespace smpl {

constexpr int V    = 6890;
constexpr int NB   = 10;
constexpr int NJ   = 24;
constexpr int NK   = 19;
constexpr int B    = 1024;

constexpr int VP   = 6912;
constexpr int M1   = 512;
constexpr int N1   = 768;
constexpr int SPLITK1 = 12;           // KSEG = 576 = 18*32
constexpr int KSEG = VP / SPLITK1;
constexpr int KQ   = 256;             // 218 padded
constexpr int N2   = 1408;            // 1368 padded

// GEMM1 fp16 operands (K = v contiguous)
__device__ __align__(256) __half g_Gh16[M1 * VP];
__device__ __align__(256) __half g_Eh16[N1 * VP];

// GEMM2 operands, K(=q) contiguous
__device__ __align__(256) __half g_A2h[B * KQ];
__device__ __align__(256) __half g_A2l[B * KQ];
__device__ __align__(256) __half g_CTt[N2 * KQ];

__device__ __align__(256) float g_Cp [SPLITK1 * M1 * N1];
__device__ __align__(256) float g_S  [456];
__device__ __align__(256) float g_JT [24 * 33];
__device__ __align__(256) float g_Rg [B * 288];
__device__ __align__(256) float g_P  [B * N2];

__constant__ int c_par[24] = {-1,0,0,0,1,2,3,4,5,6,7,8,9,9,9,12,13,14,16,17,18,19,20,21};

__device__ __forceinline__ void split_h16(float v, __half& hi, __half& lo) {
    hi = __float2half_rn(v);
    lo = __float2half_rn(v - __half2float(hi));
}

// ---------------------------------------------------------------------------
// Fused buildG: one CTA per 128-v slice; regressor columns cached in smem.
// ---------------------------------------------------------------------------
__global__ void __launch_bounds__(128) k_buildG(
        const float* __restrict__ joint_reg,
        const float* __restrict__ weights,
        const float* __restrict__ J_reg) {
    __shared__ float s_jr[NK][128];
    __shared__ float s_w [NJ][128];
    __shared__ float s_J [NJ][128];

    const int tid = threadIdx.x;
    const int v   = blockIdx.x * 128 + tid;
    if (v < V) {
#pragma unroll
        for (int c = 0; c < NK; ++c) s_jr[c][tid] = joint_reg[(size_t)v * NK + c];
#pragma unroll
        for (int c = 0; c < NJ; ++c) s_w[c][tid]  = weights[(size_t)v * NJ + c];
#pragma unroll
        for (int c = 0; c < NJ; ++c) s_J[c][tid]  = J_reg[(size_t)v * NJ + c];
    } else {
#pragma unroll
        for (int c = 0; c < NK; ++c) s_jr[c][tid] = 0.f;
#pragma unroll
        for (int c = 0; c < NJ; ++c) s_w[c][tid]  = 0.f;
#pragma unroll
        for (int c = 0; c < NJ; ++c) s_J[c][tid]  = 0.f;
    }
    __syncthreads();

    __half* dst = g_Gh16 + (blockIdx.x * 128 + tid);
    for (int k = 0; k < NK; ++k) {
        float a = s_jr[k][tid];
#pragma unroll
        for (int j = 0; j < NJ; ++j)
            dst[(size_t)(k * NJ + j) * VP] = __float2half_rn(a * s_w[j][tid]);
    }
#pragma unroll
    for (int j = 0; j < NJ; ++j)
        dst[(size_t)(456 + j) * VP] = __float2half_rn(s_J[j][tid]);
#pragma unroll
    for (int m = 480; m < M1; ++m)
        dst[(size_t)m * VP] = __float2half_rn(0.f);
}

// ---------------------------------------------------------------------------
// Merged buildE: y < 207 -> pose rows (writes rows 3p..3p+2);
//                y >= 207 -> rest row n = 621 + (y - 207).
// 192 threads, 4 v per thread.
// ---------------------------------------------------------------------------
__global__ void k_buildE(const float* __restrict__ posedirs,
                         const float* __restrict__ shapedirs,
                         const float* __restrict__ v_template) {
    const int y  = blockIdx.y;
    const int vv = (blockIdx.x * 192 + threadIdx.x) * 4;
    if (y < 207) {
        const int p = y;
        const float* src = posedirs + (size_t)p * (V * 3);
        float f[4][3];
#pragma unroll
        for (int u = 0; u < 4; ++u) {
            int v = vv + u;
#pragma unroll
            for (int c = 0; c < 3; ++c)
                f[u][c] = (v < V) ? src[3 * v + c] : 0.f;
        }
#pragma unroll
        for (int c = 0; c < 3; ++c) {
            __half* dst = g_Eh16 + (size_t)(3 * p + c) * VP + vv;
            *(__half2*)dst       = __floats2half2_rn(f[0][c], f[1][c]);
            *(__half2*)(dst + 2) = __floats2half2_rn(f[2][c], f[3][c]);
        }
    } else {
        const int n = 621 + (y - 207);
        float f[4] = {0.f, 0.f, 0.f, 0.f};
        if (n < 651) {
            int t = n - 621, q = t / 3, c = t - 3 * q;   // uniform
            const float* src = shapedirs + (size_t)q * (V * 3);
#pragma unroll
            for (int u = 0; u < 4; ++u)
                if (vv + u < V) f[u] = src[3 * (vv + u) + c];
        } else if (n < 654) {
            int c = n - 651;
#pragma unroll
            for (int u = 0; u < 4; ++u)
                if (vv + u < V) f[u] = v_template[3 * (vv + u) + c];
        } else if (n == 654) {
#pragma unroll
            for (int u = 0; u < 4; ++u)
                if (vv + u < V) f[u] = 1.f;
        }
        __half* dst = g_Eh16 + (size_t)n * VP + vv;
        *(__half2*)dst       = __floats2half2_rn(f[0], f[1]);
        *(__half2*)(dst + 2) = __floats2half2_rn(f[2], f[3]);
    }
}

// ---------------------------------------------------------------------------
// GEMM1: C[m][n] = sum_v Gh[m,v]*Eh[n,v], fp16 single term.
// CTA 256x128, BK=32, 512 threads = 16 warps as 8m x 2n (32x64 per warp),
// double-buffered dynamic smem, register prefetch, 1 sync/iter.
// ---------------------------------------------------------------------------
constexpr int G1A    = 256 * 40;               // A plane halves
constexpr int G1B    = 128 * 40;               // B plane halves
constexpr int G1_BUF = G1A + G1B;
constexpr int G1_SMEM = 2 * G1_BUF * 2;        // 61440 bytes

__global__ void __launch_bounds__(512, 1) k_gemm1_wmma() {
    using namespace nvcuda;
    extern __shared__ __align__(16) __half dynsmem[];

    const int n0    = blockIdx.x * 128;
    const int m0    = blockIdx.y * 256;
    const int split = blockIdx.z;
    const int tid   = threadIdx.x;
    const int wid   = tid >> 5;
    const int wm    = (wid & 7) * 32;
    const int wn    = (wid >> 3) * 64;

    wmma::fragment<wmma::accumulator, 16, 16, 16, float> acc[2][4];
#pragma unroll
    for (int i = 0; i < 2; ++i)
#pragma unroll
        for (int j = 0; j < 4; ++j)
            wmma::fill_fragment(acc[i][j], 0.f);

    const int kbase = split * KSEG;
    const int nIter = KSEG / 32;               // 18

    const int rA0 = tid >> 2;                  // 0..127
    const int cA  = (tid & 3) * 8;

    uint4 pA[2], pB;

    auto ldg_tile = [&](int kk) {
#pragma unroll
        for (int i = 0; i < 2; ++i) {
            int row = rA0 + 128 * i;
            pA[i] = *(const uint4*)(g_Gh16 + (size_t)(m0 + row) * VP + kk + cA);
        }
        pB = *(const uint4*)(g_Eh16 + (size_t)(n0 + rA0) * VP + kk + cA);
    };
    auto sts_tile = [&](int buf) {
        __half* base = dynsmem + buf * G1_BUF;
#pragma unroll
        for (int i = 0; i < 2; ++i) {
            int row = rA0 + 128 * i;
            *(uint4*)(base + row * 40 + cA) = pA[i];
        }
        *(uint4*)(base + G1A + rA0 * 40 + cA) = pB;
    };

    ldg_tile(kbase);
    sts_tile(0);
    ldg_tile(kbase + 32);
    __syncthreads();

    for (int it = 0; it < nIter; ++it) {
        const int cur = it & 1;
        if (it + 1 < nIter) sts_tile(1 - cur);
        if (it + 2 < nIter) ldg_tile(kbase + (it + 2) * 32);

        const __half* Ah = dynsmem + cur * G1_BUF;
        const __half* Bh = Ah + G1A;
#pragma unroll
        for (int k0 = 0; k0 < 32; k0 += 16) {
            wmma::fragment<wmma::matrix_a, 16, 16, 16, __half,
                           wmma::row_major> ah[2];
            wmma::fragment<wmma::matrix_b, 16, 16, 16, __half,
                           wmma::col_major> bh[4];
#pragma unroll
            for (int i = 0; i < 2; ++i)
                wmma::load_matrix_sync(ah[i], Ah + (wm + i * 16) * 40 + k0, 40);
#pragma unroll
            for (int j = 0; j < 4; ++j)
                wmma::load_matrix_sync(bh[j], Bh + (wn + j * 16) * 40 + k0, 40);
#pragma unroll
            for (int i = 0; i < 2; ++i)
#pragma unroll
                for (int j = 0; j < 4; ++j)
                    wmma::mma_sync(acc[i][j], ah[i], bh[j], acc[i][j]);
        }
        __syncthreads();
    }

    float* Co = g_Cp + (size_t)split * (M1 * N1);
#pragma unroll
    for (int i = 0; i < 2; ++i)
#pragma unroll
        for (int j = 0; j < 4; ++j)
            wmma::store_matrix_sync(
                &Co[(size_t)(m0 + wm + i * 16) * N1 + n0 + wn + j * 16],
                acc[i][j], N1, wmma::mem_row_major);
}

// ---------------------------------------------------------------------------
// Reduce: per-kj-row blocks; emits CTt[m][q] (fp16 K-contiguous), S, JT.
// ---------------------------------------------------------------------------
__global__ void __launch_bounds__(128) k_reduce() {
    const int blk = blockIdx.x;
    const int tid = threadIdx.x;

    if (blk < 456) {
        __shared__ float s[656];
        for (int col = tid; col < 655; col += 128) {
            float val = 0.f;
            size_t off = (size_t)blk * N1 + col;
#pragma unroll
            for (int sp = 0; sp < SPLITK1; ++sp)
                val += g_Cp[(size_t)sp * (M1 * N1) + off];
            s[col] = val;
        }
        __syncthreads();
#pragma unroll
        for (int c = 0; c < 3; ++c) {
            int m = 3 * blk + c;
            for (int q = tid; q < KQ; q += 128) {
                float val = 0.f;
                if (q == 0)        val = s[651 + c];
                else if (q <= 10)  val = s[621 + (q - 1) * 3 + c];
                else if (q < 218)  val = s[(q - 11) * 3 + c];
                g_CTt[(size_t)m * KQ + q] = __float2half_rn(val);
            }
        }
        if (tid == 0) g_S[blk] = s[654];
    } else if (blk < 480) {
        int j = blk - 456;
        if (tid < 33) {
            float val = 0.f;
            size_t off = (size_t)(456 + j) * N1 + 621 + tid;
#pragma unroll
            for (int sp = 0; sp < SPLITK1; ++sp)
                val += g_Cp[(size_t)sp * (M1 * N1) + off];
            g_JT[j * 33 + tid] = val;
        }
    } else {
        int m = 1368 + (blk - 480);
        for (int q = tid; q < KQ; q += 128)
            g_CTt[(size_t)m * KQ + q] = __float2half_rn(0.f);
    }
}

// ---------------------------------------------------------------------------
// Per-body prep (one warp / body). Emits A2 row [b][q] as fp16 hi/lo.
// ---------------------------------------------------------------------------
__global__ void k_prep(const float* __restrict__ beta,
                       const float* __restrict__ theta) {
    const int b = blockIdx.x;
    const int lane = threadIdx.x;

    __shared__ float Rsm[24][9];
    __shared__ float Jm[24][3];
    __shared__ float Ag[24][12];
    __shared__ float bet[10];

    if (lane < 10) bet[lane] = beta[b * NB + lane];
    __syncwarp();

    if (lane < 24) {
        float tx = theta[b * 72 + lane * 3 + 0];
        float ty = theta[b * 72 + lane * 3 + 1];
        float tz = theta[b * 72 + lane * 3 + 2];
        float ax = tx + 1e-8f, ay = ty + 1e-8f, az = tz + 1e-8f;
        float angle = sqrtf(ax * ax + ay * ay + az * az);
        float half = 0.5f * angle;
        float s = sinf(half), cw = cosf(half);
        float vx = tx / angle * s, vy = ty / angle * s, vz = tz / angle * s;
        float qn = sqrtf(cw * cw + vx * vx + vy * vy + vz * vz);
        float w = cw / qn, x = vx / qn, y = vy / qn, z = vz / qn;
        Rsm[lane][0] = 1.f - 2.f * (y * y + z * z);
        Rsm[lane][1] = 2.f * (x * y - w * z);
        Rsm[lane][2] = 2.f * (x * z + w * y);
        Rsm[lane][3] = 2.f * (x * y + w * z);
        Rsm[lane][4] = 1.f - 2.f * (x * x + z * z);
        Rsm[lane][5] = 2.f * (y * z - w * x);
        Rsm[lane][6] = 2.f * (x * z - w * y);
        Rsm[lane][7] = 2.f * (y * z + w * x);
        Rsm[lane][8] = 1.f - 2.f * (x * x + y * y);
#pragma unroll
        for (int c = 0; c < 3; ++c) {
            float val = g_JT[lane * 33 + 30 + c];
#pragma unroll
            for (int n = 0; n < 10; ++n)
                val += bet[n] * g_JT[lane * 33 + n * 3 + c];
            Jm[lane][c] = val;
        }
    }
    __syncwarp();

    for (int q = lane; q < KQ; q += 32) {
        float val;
        if (q == 0) val = 1.f;
        else if (q <= 10) val = bet[q - 1];
        else if (q < 218) {
            int p = q - 11;
            int i = p / 9 + 1, e = p - 9 * (p / 9);
            val = Rsm[i][e] - ((e == 0 || e == 4 || e == 8) ? 1.f : 0.f);
        } else val = 0.f;
        __half hi, lo;
        split_h16(val, hi, lo);
        g_A2h[(size_t)b * KQ + q] = hi;
        g_A2l[(size_t)b * KQ + q] = lo;
    }

    const int r = lane >> 2, cc = lane & 3;
    for (int i = 0; i < 24; ++i) {
        if (lane < 12) {
            float val;
            if (i == 0) {
                val = (cc < 3) ? Rsm[0][r * 3 + cc] * (cc == 0 ? 1.f : -1.f)
                               : Jm[0][r];
            } else {
                int par = c_par[i];
                float l0, l1, l2;
                if (cc < 3) {
                    l0 = Rsm[i][0 * 3 + cc];
                    l1 = Rsm[i][1 * 3 + cc];
                    l2 = Rsm[i][2 * 3 + cc];
                } else {
                    l0 = Jm[i][0] - Jm[par][0];
                    l1 = Jm[i][1] - Jm[par][1];
                    l2 = Jm[i][2] - Jm[par][2];
                }
                val = Ag[par][r * 4 + 0] * l0 + Ag[par][r * 4 + 1] * l1 +
                      Ag[par][r * 4 + 2] * l2;
                if (cc == 3) val += Ag[par][r * 4 + 3];
            }
            Ag[i][r * 4 + cc] = val;
        }
        __syncwarp();
    }

    for (int idx = lane; idx < 288; idx += 32) {
        int j = idx / 12, e = idx - 12 * j;
        float out;
        if (e < 9) {
            int rr = e / 3, c = e - 3 * rr;
            out = Ag[j][rr * 4 + c];
        } else {
            int rr = e - 9;
            out = Ag[j][rr * 4 + 3] -
                  (Ag[j][rr * 4 + 0] * Jm[j][0] + Ag[j][rr * 4 + 1] * Jm[j][1] +
                   Ag[j][rr * 4 + 2] * Jm[j][2]);
        }
        g_Rg[b * 288 + idx] = out;
    }
}

// ---------------------------------------------------------------------------
// GEMM2: P[b][m] = sum_q A2[b,q]*CTt[m,q], fp16 2-term, split-K = 1.
// CTA 128x128, BK=32, 8 warps as 4b x 2m (32x64 per warp).
// ---------------------------------------------------------------------------
__global__ void __launch_bounds__(256, 2) k_gemm2_wmma() {
    using namespace nvcuda;

    __shared__ __align__(16) __half Ash[128][40];
    __shared__ __align__(16) __half Asl[128][40];
    __shared__ __align__(16) __half Bs [128][40];

    const int n0  = blockIdx.x * 128;
    const int b0  = blockIdx.y * 128;
    const int tid = threadIdx.x;
    const int wid = tid >> 5;
    const int wb  = (wid & 3) * 32;
    const int wn  = (wid >> 2) * 64;

    wmma::fragment<wmma::accumulator, 16, 16, 16, float> acc[2][4];
#pragma unroll
    for (int i = 0; i < 2; ++i)
#pragma unroll
        for (int j = 0; j < 4; ++j)
            wmma::fill_fragment(acc[i][j], 0.f);

    const int nIter = KQ / 32;                 // 8

    uint4 pAh[2], pAl[2], pB[2];
    auto ldg_tile = [&](int kk) {
#pragma unroll
        for (int i = 0; i < 2; ++i) {
            int linear = tid + 256 * i;
            int row = linear >> 2, c = (linear & 3) * 8;
            pAh[i] = *(const uint4*)(g_A2h + (size_t)(b0 + row) * KQ + kk + c);
            pAl[i] = *(const uint4*)(g_A2l + (size_t)(b0 + row) * KQ + kk + c);
            pB[i]  = *(const uint4*)(g_CTt + (size_t)(n0 + row) * KQ + kk + c);
        }
    };

    ldg_tile(0);

    for (int it = 0; it < nIter; ++it) {
        __syncthreads();
#pragma unroll
        for (int i = 0; i < 2; ++i) {
            int linear = tid + 256 * i;
            int row = linear >> 2, c = (linear & 3) * 8;
            *(uint4*)&Ash[row][c] = pAh[i];
            *(uint4*)&Asl[row][c] = pAl[i];
            *(uint4*)&Bs[row][c]  = pB[i];
        }
        __syncthreads();
        if (it + 1 < nIter) ldg_tile((it + 1) * 32);

#pragma unroll
        for (int k0 = 0; k0 < 32; k0 += 16) {
            wmma::fragment<wmma::matrix_a, 16, 16, 16, __half,
                           wmma::row_major> ah[2], al[2];
            wmma::fragment<wmma::matrix_b, 16, 16, 16, __half,
                           wmma::col_major> bh[4];
#pragma unroll
            for (int i = 0; i < 2; ++i) {
                wmma::load_matrix_sync(ah[i], &Ash[wb + i * 16][k0], 40);
                wmma::load_matrix_sync(al[i], &Asl[wb + i * 16][k0], 40);
            }
#pragma unroll
            for (int j = 0; j < 4; ++j)
                wmma::load_matrix_sync(bh[j], &Bs[wn + j * 16][k0], 40);
#pragma unroll
            for (int i = 0; i < 2; ++i)
#pragma unroll
                for (int j = 0; j < 4; ++j) {
                    wmma::mma_sync(acc[i][j], ah[i], bh[j], acc[i][j]);
                    wmma::mma_sync(acc[i][j], al[i], bh[j], acc[i][j]);
                }
        }
    }

#pragma unroll
    for (int i = 0; i < 2; ++i)
#pragma unroll
        for (int j = 0; j < 4; ++j)
            wmma::store_matrix_sync(
                &g_P[(size_t)(b0 + wb + i * 16) * N2 + n0 + wn + j * 16],
                acc[i][j], N2, wmma::mem_row_major);
}

// ---------------------------------------------------------------------------
// joints epilogue
// ---------------------------------------------------------------------------
__global__ void k_joints(const float* __restrict__ trans,
                         float* __restrict__ out) {
    const int b = blockIdx.x;
    const int tid = threadIdx.x;
    __shared__ float sA[288];
    __shared__ float sS[456];
    for (int i = tid; i < 288; i += 64) sA[i] = g_Rg[b * 288 + i];
    for (int i = tid; i < 456; i += 64) sS[i] = g_S[i];
    __syncthreads();
    if (tid < 57) {
        int k = tid / 3, r = tid - 3 * k;
        float acc = trans[b * 3 + r];
        const float* Pb = &g_P[(size_t)b * N2];
#pragma unroll
        for (int j = 0; j < 24; ++j) {
            const float* M = &sA[j * 12];
            int m = (k * 24 + j) * 3;
            float p0 = Pb[m + 0], p1 = Pb[m + 1], p2 = Pb[m + 2];
            acc += M[r * 3 + 0] * p0 + M[r * 3 + 1] * p1 + M[r * 3 + 2] * p2 +
                   M[9 + r] * sS[k * 24 + j];
        }
        out[b * 57 + tid] = acc;
    }
}

} // namespace smpl

extern "C" void kernel_launch(void* const* d_in, const int* in_sizes, int n_in,
                              void* d_out, int out_size) {
    using namespace smpl;
    const float* beta       = (const float*)d_in[0];
    const float* theta      = (const float*)d_in[1];
    const float* trans      = (const float*)d_in[2];
    const float* v_template = (const float*)d_in[3];
    const float* shapedirs  = (const float*)d_in[4];
    const float* J_reg      = (const float*)d_in[5];
    const float* posedirs   = (const float*)d_in[6];
    const float* joint_reg  = (const float*)d_in[7];
    const float* weights    = (const float*)d_in[8];
    float* out = (float*)d_out;

    cudaFuncSetAttribute(k_gemm1_wmma,
                         cudaFuncAttributeMaxDynamicSharedMemorySize, G1_SMEM);

    // 1) Build fp16 operands
    k_buildG<<<VP / 128, 128>>>(joint_reg, weights, J_reg);
    {
        dim3 grid(VP / 768, 354);                 // 9 x (207 pose + 147 rest)
        k_buildE<<<grid, 192>>>(posedirs, shapedirs, v_template);
    }

    // 2) GEMM1 fp16 single-term, 256x128 tiles, 512 thr, split-K = 12
    {
        dim3 grid(N1 / 128, M1 / 256, SPLITK1);   // 6 x 2 x 12 = 144 CTAs
        k_gemm1_wmma<<<grid, 512, G1_SMEM>>>();
    }

    // 3) Reduce partials -> CTt / S / JT
    k_reduce<<<520, 128>>>();

    // 4) Per-body prep
    k_prep<<<B, 32>>>(beta, theta);

    // 5) GEMM2 fp16 2-term, split-K = 1
    {
        dim3 grid(N2 / 128, B / 128);             // 11 x 8
        k_gemm2_wmma<<<grid, 256>>>();
    }

    // 6) Joints epilogue
    k_joints<<<B, 64>>>(trans, out);
}